// round 3
// baseline (speedup 1.0000x reference)
#include <cuda_runtime.h>

// ---------------- problem constants ----------------
#define BB   4
#define CC   64
#define HH   180
#define WW   320
#define HW   57600          // H*W
#define WT   80             // width tile per CTA (8 sub-chunks of 10)
#define PIT  81             // smem pitch (conflict-free)
#define NSUB 8
#define EPSV 1e-6f

// ---------------- device scratch (no allocations allowed) ----------------
__device__ float g_gap [2*BB*CC];        // [side][b][c]  side0=x_l, side1=x_r
__device__ float g_WT1 [2*CC*CC];        // [side][c][o]  p1_w * norm_w, transposed
__device__ float g_b1  [2*CC];
__device__ float g_rs1 [2*CC];
__device__ float g_Weff[2*BB*CC*CC];     // [side*4+b][o][i]
__device__ float g_bagg[2*BB*CC];
__device__ float g_MT  [2*BB*CC*CC];     // [side*4+b][c][o]  (Weff @ p2_w)^T
__device__ float g_cvec[2*BB*CC];        // Weff@p2_b + bagg

// ---------------- prepass 1: global average pool ----------------
__global__ void k_gap(const float* __restrict__ xl, const float* __restrict__ xr) {
    int id = blockIdx.x;                         // 0..511
    const float* x = (id < BB*CC) ? xl : xr;
    int rem = id % (BB*CC);
    const float4* p = reinterpret_cast<const float4*>(x + (size_t)rem * HW);
    float s = 0.f;
    for (int i = threadIdx.x; i < HW/4; i += blockDim.x) {
        float4 v = p[i];
        s += (v.x + v.y) + (v.z + v.w);
    }
    __shared__ float red[32];
    for (int o = 16; o; o >>= 1) s += __shfl_down_sync(0xffffffffu, s, o);
    if ((threadIdx.x & 31) == 0) red[threadIdx.x >> 5] = s;
    __syncthreads();
    if (threadIdx.x < 8) {
        s = red[threadIdx.x];
        for (int o = 4; o; o >>= 1) s += __shfl_down_sync(0xffu, s, o);
        if (threadIdx.x == 0) g_gap[id] = s * (1.f / HW);
    }
}

// ---------------- prepass 2: fold LN into Q projection ----------------
__global__ void k_fold(const float* __restrict__ lp1w, const float* __restrict__ lp1b,
                       const float* __restrict__ rp1w, const float* __restrict__ rp1b,
                       const float* __restrict__ nlw,  const float* __restrict__ nlb,
                       const float* __restrict__ nrw,  const float* __restrict__ nrb) {
    int t = threadIdx.x;
    if (t >= 128) return;
    int side = t >> 6, o = t & 63;
    const float* pw = side ? rp1w : lp1w;
    const float* pb = side ? rp1b : lp1b;
    const float* nw = side ? nrw  : nlw;
    const float* nb = side ? nrb  : nlb;
    float b1 = pb[o], rs = 0.f;
    for (int c = 0; c < CC; c++) {
        float wv = pw[o*CC + c] * nw[c];
        g_WT1[side*CC*CC + c*CC + o] = wv;
        rs += wv;
        b1 += pw[o*CC + c] * nb[c];
    }
    g_b1[side*CC + o] = b1;
    g_rs1[side*CC + o] = rs;
}

// ---------------- prepass 3: attention mixture -> Weff, bagg ----------------
__global__ void k_att(const float* __restrict__ lf1w, const float* __restrict__ lf1b,
                      const float* __restrict__ lf2w, const float* __restrict__ lf2b,
                      const float* __restrict__ lW,   const float* __restrict__ lbias,
                      const float* __restrict__ rf1w, const float* __restrict__ rf1b,
                      const float* __restrict__ rf2w, const float* __restrict__ rf2b,
                      const float* __restrict__ rW,   const float* __restrict__ rbias,
                      const float* __restrict__ beta, const float* __restrict__ gamma) {
    int sb = blockIdx.x;                 // side*4 + b
    int side = sb >> 2, b = sb & 3;
    const float* f1w  = side ? rf1w  : lf1w;
    const float* f1b  = side ? rf1b  : lf1b;
    const float* f2w  = side ? rf2w  : lf2w;
    const float* f2b  = side ? rf2b  : lf2b;
    const float* Wk   = side ? rW    : lW;
    const float* bias = side ? rbias : lbias;
    const float* bg   = side ? gamma : beta;
    const float* gap  = g_gap + side*BB*CC + b*CC;

    float a1[3];
    #pragma unroll
    for (int k = 0; k < 3; k++) {
        float s = f1b[k];
        for (int c = 0; c < CC; c++) s += f1w[k*CC + c] * gap[c];
        a1[k] = fmaxf(s, 0.f);
    }
    float a2[3];
    #pragma unroll
    for (int k = 0; k < 3; k++) {
        float s = f2b[k];
        #pragma unroll
        for (int j = 0; j < 3; j++) s += f2w[k*3 + j] * a1[j];
        a2[k] = s;
    }
    float mx = fmaxf(a2[0], fmaxf(a2[1], a2[2]));
    float e0 = expf(a2[0]-mx), e1 = expf(a2[1]-mx), e2 = expf(a2[2]-mx);
    float inv = 1.f / (e0 + e1 + e2);
    float at0 = e0*inv, at1 = e1*inv, at2 = e2*inv;

    for (int idx = threadIdx.x; idx < CC*CC; idx += blockDim.x) {
        int i = idx & 63;
        float w = (at0*Wk[idx] + at1*Wk[CC*CC + idx] + at2*Wk[2*CC*CC + idx]) * bg[i];
        g_Weff[sb*CC*CC + idx] = w;
    }
    if (threadIdx.x < CC) {
        int o = threadIdx.x;
        g_bagg[sb*CC + o] = at0*bias[o] + at1*bias[CC + o] + at2*bias[2*CC + o];
    }
}

// ---------------- prepass 4: M = Weff @ p2_w (transposed), cvec ----------------
__global__ void k_mt(const float* __restrict__ rp2w, const float* __restrict__ rp2b,
                     const float* __restrict__ lp2w, const float* __restrict__ lp2b) {
    int sb = blockIdx.x;
    int side = sb >> 2;
    const float* p2w = side ? lp2w : rp2w;   // out_l path consumes V_r (rp2)!
    const float* p2b = side ? lp2b : rp2b;
    const float* We  = g_Weff + sb*CC*CC;

    for (int idx = threadIdx.x; idx < CC*CC; idx += blockDim.x) {
        int c = idx >> 6, o = idx & 63;
        float s = 0.f;
        for (int i = 0; i < CC; i++) s += We[o*CC + i] * p2w[i*CC + c];
        g_MT[sb*CC*CC + idx] = s;            // [c][o]
    }
    if (threadIdx.x < CC) {
        int o = threadIdx.x;
        float s = g_bagg[sb*CC + o];
        for (int i = 0; i < CC; i++) s += We[o*CC + i] * p2b[i];
        g_cvec[sb*CC + o] = s;
    }
}

// ---------------- fused main kernel ----------------
// One 64x64 @ 64x80 GEMM micro-kernel: threads as 16(oq) x 16(wq); each thread
// computes a 4(o) x 5(w) tile. WTm is [c][o] so the 4 o-values are one float4.
__device__ __forceinline__ void gemm_tile(
    const float* __restrict__ WTm, const float* __restrict__ xs,
    float* __restrict__ os,
    const float* mu, const float* iv,
    const float* __restrict__ rs, const float* __restrict__ b1, int tid)
{
    int oq = tid >> 4, wq = tid & 15;
    int o0 = oq << 2, w0 = wq * 5;
    float acc[4][5];
    #pragma unroll
    for (int i = 0; i < 4; i++)
        #pragma unroll
        for (int j = 0; j < 5; j++) acc[i][j] = 0.f;

    #pragma unroll 8
    for (int c = 0; c < CC; c++) {
        float4 wv = *reinterpret_cast<const float4*>(WTm + (c << 6) + o0);
        const float* xc = xs + c*PIT + w0;
        float x0 = xc[0], x1 = xc[1], x2 = xc[2], x3 = xc[3], x4 = xc[4];
        float wr[4] = {wv.x, wv.y, wv.z, wv.w};
        #pragma unroll
        for (int i = 0; i < 4; i++) {
            acc[i][0] += wr[i]*x0; acc[i][1] += wr[i]*x1; acc[i][2] += wr[i]*x2;
            acc[i][3] += wr[i]*x3; acc[i][4] += wr[i]*x4;
        }
    }
    if (mu) {   // Q epilogue: fold LayerNorm
        #pragma unroll
        for (int i = 0; i < 4; i++) {
            float rsv = rs[o0+i], bv = b1[o0+i];
            #pragma unroll
            for (int j = 0; j < 5; j++) {
                int w = w0 + j;
                os[(o0+i)*PIT + w] = iv[w]*(acc[i][j] - mu[w]*rsv) + bv;
            }
        }
    } else {
        #pragma unroll
        for (int i = 0; i < 4; i++)
            #pragma unroll
            for (int j = 0; j < 5; j++)
                os[(o0+i)*PIT + w0 + j] = acc[i][j];
    }
}

__global__ void __launch_bounds__(256, 2) k_main(
    const float* __restrict__ xl_g, const float* __restrict__ xr_g,
    float* __restrict__ out)
{
    extern __shared__ float sm[];
    float* xls  = sm;
    float* xrs  = sm + 1*CC*PIT;
    float* qa   = sm + 2*CC*PIT;   // Ql then Pr
    float* qb   = sm + 3*CC*PIT;   // Qr then Pl
    float* mul  = sm + 4*CC*PIT;
    float* invl = mul  + WT;
    float* mur  = invl + WT;
    float* invr = mur  + WT;
    float* Ssm  = invr + WT;       // 800
    float* Ar   = Ssm  + NSUB*100; // 800
    float* Al   = Ar   + NSUB*100; // 800

    int gid = blockIdx.x;
    int g   = gid & 3;
    int h   = (gid >> 2) % HH;
    int b   = gid / (4*HH);
    int tid = threadIdx.x;
    size_t base = (size_t)b * (CC*HW) + (size_t)h * WW + (size_t)g * WT;

    // stage 1: load tiles
    for (int idx = tid; idx < CC*WT; idx += 256) {
        int c = idx / WT, w = idx - c*WT;
        size_t go = base + (size_t)c*HW + w;
        xls[c*PIT + w] = xl_g[go];
        xrs[c*PIT + w] = xr_g[go];
    }
    __syncthreads();

    // stage 2: per-column LN stats
    if (tid < 2*WT) {
        int side = tid / WT, w = tid - side*WT;
        const float* xs = side ? xrs : xls;
        float s = 0.f, s2 = 0.f;
        #pragma unroll
        for (int c = 0; c < CC; c++) {
            float v = xs[c*PIT + w];
            s += v; s2 += v*v;
        }
        float mu  = s * (1.f/CC);
        float var = s2 * (1.f/CC) - mu*mu;
        float ivv = rsqrtf(var + EPSV);
        if (side) { mur[w] = mu; invr[w] = ivv; }
        else      { mul[w] = mu; invl[w] = ivv; }
    }
    __syncthreads();

    // stage 3: Q projections (LN folded)
    gemm_tile(g_WT1,        xls, qa, mul, invl, g_rs1,      g_b1,      tid);
    gemm_tile(g_WT1 + CC*CC, xrs, qb, mur, invr, g_rs1 + CC, g_b1 + CC, tid);
    __syncthreads();

    // stage 4: attention scores (2x2 blocks, 200 threads)
    if (tid < 200) {
        int n = tid / 25, r = tid - 25*n;
        int u0 = (r/5)*2, v0 = (r%5)*2;
        const float* A_ = qa + n*10;
        const float* B_ = qb + n*10;
        float a00=0, a01=0, a10=0, a11=0;
        #pragma unroll 8
        for (int o = 0; o < CC; o++) {
            float l0 = A_[o*PIT + u0], l1 = A_[o*PIT + u0 + 1];
            float r0 = B_[o*PIT + v0], r1 = B_[o*PIT + v0 + 1];
            a00 += l0*r0; a01 += l0*r1; a10 += l1*r0; a11 += l1*r1;
        }
        float* Sp = Ssm + n*100;
        const float sc = 0.125f;          // C^-0.5
        Sp[ u0   *10 + v0    ] = a00*sc;
        Sp[ u0   *10 + v0 + 1] = a01*sc;
        Sp[(u0+1)*10 + v0    ] = a10*sc;
        Sp[(u0+1)*10 + v0 + 1] = a11*sc;
    }
    __syncthreads();

    // stage 5: dual softmax (rows -> Ar, cols -> Al)
    if (tid < 80) {
        int n = tid / 10, u = tid - 10*n;
        const float* Sp = Ssm + n*100 + u*10;
        float m = Sp[0];
        #pragma unroll
        for (int v = 1; v < 10; v++) m = fmaxf(m, Sp[v]);
        float e[10], s = 0.f;
        #pragma unroll
        for (int v = 0; v < 10; v++) { e[v] = __expf(Sp[v]-m); s += e[v]; }
        float inv = 1.f/s;
        float* dst = Ar + n*100 + u*10;
        #pragma unroll
        for (int v = 0; v < 10; v++) dst[v] = e[v]*inv;
    } else if (tid < 160) {
        int t = tid - 80;
        int n = t / 10, v = t - 10*n;
        const float* Sp = Ssm + n*100 + v;
        float m = Sp[0];
        #pragma unroll
        for (int u = 1; u < 10; u++) m = fmaxf(m, Sp[u*10]);
        float e[10], s = 0.f;
        #pragma unroll
        for (int u = 0; u < 10; u++) { e[u] = __expf(Sp[u*10]-m); s += e[u]; }
        float inv = 1.f/s;
        float* dst = Al + n*100 + v;
        #pragma unroll
        for (int u = 0; u < 10; u++) dst[u*10] = e[u]*inv;
    }
    __syncthreads();

    // stage 6: P projections (dynamic-conv matrices pre-folded)
    gemm_tile(g_MT + (0*BB + b)*CC*CC, xrs, qa, nullptr, nullptr, nullptr, nullptr, tid); // Pr
    gemm_tile(g_MT + (1*BB + b)*CC*CC, xls, qb, nullptr, nullptr, nullptr, nullptr, tid); // Pl
    __syncthreads();

    // stage 7: aggregate + residual, in place into xls/xrs
    {
        int oq = tid >> 4, wq = tid & 15;
        int o0 = oq << 2, w0 = wq * 5;
        int n  = w0 / 10;
        int ub = w0 - n*10;                  // 0 or 5
        const float* Arn = Ar + n*100;
        const float* Aln = Al + n*100;
        #pragma unroll
        for (int i = 0; i < 4; i++) {
            int o = o0 + i;
            float cl = g_cvec[b*CC + o];
            float cr = g_cvec[(BB + b)*CC + o];
            float pr[10], pl[10];
            #pragma unroll
            for (int v = 0; v < 10; v++) {
                pr[v] = qa[o*PIT + n*10 + v];
                pl[v] = qb[o*PIT + n*10 + v];
            }
            #pragma unroll
            for (int j = 0; j < 5; j++) {
                int u = ub + j;
                float sl = cl, sr = cr;
                #pragma unroll
                for (int v = 0; v < 10; v++) {
                    sl += Arn[u*10 + v] * pr[v];   // out_l[o,u] = sum_v A_r2l[u,v] Pr[o,v]
                    sr += Aln[v*10 + u] * pl[v];   // out_r[o,u] = sum_uu A_l2r[uu,u] Pl[o,uu]
                }
                xls[o*PIT + w0 + j] += sl;
                xrs[o*PIT + w0 + j] += sr;
            }
        }
    }
    __syncthreads();

    // stage 8: coalesced writeback
    const size_t OUTOFF = (size_t)BB*CC*HW;
    for (int idx = tid; idx < CC*WT; idx += 256) {
        int c = idx / WT, w = idx - c*WT;
        size_t go = base + (size_t)c*HW + w;
        out[go]          = xls[c*PIT + w];
        out[OUTOFF + go] = xrs[c*PIT + w];
    }
}

// ---------------- launch ----------------
extern "C" void kernel_launch(void* const* d_in, const int* in_sizes, int n_in,
                              void* d_out, int out_size) {
    const float* xl    = (const float*)d_in[0];
    const float* xr    = (const float*)d_in[1];
    const float* nlw   = (const float*)d_in[2];
    const float* nlb   = (const float*)d_in[3];
    const float* nrw   = (const float*)d_in[4];
    const float* nrb   = (const float*)d_in[5];
    const float* lp1w  = (const float*)d_in[6];
    const float* lp1b  = (const float*)d_in[7];
    const float* rp1w  = (const float*)d_in[8];
    const float* rp1b  = (const float*)d_in[9];
    const float* lp2w  = (const float*)d_in[10];
    const float* lp2b  = (const float*)d_in[11];
    const float* rp2w  = (const float*)d_in[12];
    const float* rp2b  = (const float*)d_in[13];
    const float* beta  = (const float*)d_in[14];
    const float* gamma = (const float*)d_in[15];
    const float* lf1w  = (const float*)d_in[16];
    const float* lf1b  = (const float*)d_in[17];
    const float* lf2w  = (const float*)d_in[18];
    const float* lf2b  = (const float*)d_in[19];
    const float* lW    = (const float*)d_in[20];
    const float* lbias = (const float*)d_in[21];
    const float* rf1w  = (const float*)d_in[22];
    const float* rf1b  = (const float*)d_in[23];
    const float* rf2w  = (const float*)d_in[24];
    const float* rf2b  = (const float*)d_in[25];
    const float* rW    = (const float*)d_in[26];
    const float* rbias = (const float*)d_in[27];
    float* out = (float*)d_out;

    const int SMEM_BYTES = (4*CC*PIT + 4*WT + 3*NSUB*100) * sizeof(float); // 93,824

    cudaFuncSetAttribute(k_main, cudaFuncAttributeMaxDynamicSharedMemorySize, SMEM_BYTES);

    k_gap <<<2*BB*CC, 256>>>(xl, xr);
    k_fold<<<1, 128>>>(lp1w, lp1b, rp1w, rp1b, nlw, nlb, nrw, nrb);
    k_att <<<2*BB, 256>>>(lf1w, lf1b, lf2w, lf2b, lW, lbias,
                          rf1w, rf1b, rf2w, rf2b, rW, rbias, beta, gamma);
    k_mt  <<<2*BB, 256>>>(rp2w, rp2b, lp2w, lp2b);
    k_main<<<BB*HH*(WW/WT), 256, SMEM_BYTES>>>(xl, xr, out);
}

// round 5
// speedup vs baseline: 2.0366x; 2.0366x over previous
#include <cuda_runtime.h>

// ---------------- problem constants ----------------
#define BB   4
#define CC   64
#define HH   180
#define WW   320
#define HW   57600          // H*W
#define WT   80             // width tile per CTA (8 sub-chunks of 10)
#define PIT  81             // smem pitch (conflict-free)
#define NSUB 8
#define EPSV 1e-6f

// ---------------- device scratch (no allocations allowed) ----------------
__device__ float g_gap [2*BB*CC];        // [side][b][c]  side0=x_l, side1=x_r
__device__ float g_WT1 [2*CC*CC];        // [side][c][o]  p1_w * norm_w, transposed
__device__ float g_b1  [2*CC];
__device__ float g_rs1 [2*CC];
__device__ float g_MT  [2*BB*CC*CC];     // [side*4+b][c][o]  (Weff @ p2_w)^T
__device__ float g_cvec[2*BB*CC];        // Weff@p2_b + bagg

// ---------------- prepass 1: global average pool ----------------
__global__ void k_gap(const float* __restrict__ xl, const float* __restrict__ xr) {
    int id = blockIdx.x;                         // 0..511
    const float* x = (id < BB*CC) ? xl : xr;
    int rem = id % (BB*CC);
    const float4* p = reinterpret_cast<const float4*>(x + (size_t)rem * HW);
    float s = 0.f;
    for (int i = threadIdx.x; i < HW/4; i += blockDim.x) {
        float4 v = p[i];
        s += (v.x + v.y) + (v.z + v.w);
    }
    __shared__ float red[32];
    for (int o = 16; o; o >>= 1) s += __shfl_down_sync(0xffffffffu, s, o);
    if ((threadIdx.x & 31) == 0) red[threadIdx.x >> 5] = s;
    __syncthreads();
    if (threadIdx.x < 8) {
        s = red[threadIdx.x];
        for (int o = 4; o; o >>= 1) s += __shfl_down_sync(0xffu, s, o);
        if (threadIdx.x == 0) g_gap[id] = s * (1.f / HW);
    }
}

// ---------------- prepass 2: everything else, properly parallel ----------------
// grid = 10 blocks x 256 threads.
//   blocks 0..7  : sb = side*4+b  -> att mixture, Weff (smem), MT = Weff@p2w, cvec
//   blocks 8..9  : side = bid-8   -> LN fold into Q projection (WT1, b1, rs1)
#define WEP 65   // smem pitch for Weff (bank-conflict-free column reads)

__global__ void __launch_bounds__(256) k_prep(
    const float* __restrict__ lp1w, const float* __restrict__ lp1b,
    const float* __restrict__ rp1w, const float* __restrict__ rp1b,
    const float* __restrict__ nlw,  const float* __restrict__ nlb,
    const float* __restrict__ nrw,  const float* __restrict__ nrb,
    const float* __restrict__ lp2w, const float* __restrict__ lp2b,
    const float* __restrict__ rp2w, const float* __restrict__ rp2b,
    const float* __restrict__ beta, const float* __restrict__ gamma,
    const float* __restrict__ lf1w, const float* __restrict__ lf1b,
    const float* __restrict__ lf2w, const float* __restrict__ lf2b,
    const float* __restrict__ lW,   const float* __restrict__ lbias,
    const float* __restrict__ rf1w, const float* __restrict__ rf1b,
    const float* __restrict__ rf2w, const float* __restrict__ rf2b,
    const float* __restrict__ rW,   const float* __restrict__ rbias)
{
    __shared__ float sWe[CC*WEP];    // Weff, pitch 65
    __shared__ float sPs[CC*CC];     // p2w staged
    __shared__ float sA1[3];
    __shared__ float sAtt[3];

    const int tid  = threadIdx.x;
    const int lane = tid & 31;
    const int wid  = tid >> 5;
    const int bid  = blockIdx.x;

    // ======== blocks 8,9: LN fold ========
    if (bid >= 8) {
        int side = bid - 8;
        const float* pw = side ? rp1w : lp1w;
        const float* pb = side ? rp1b : lp1b;
        const float* nw = side ? nrw  : nlw;
        const float* nb = side ? nrb  : nlb;

        // g_WT1 elementwise: WT1[c][o] = pw[o][c]*nw[c]
        for (int idx = tid; idx < CC*CC; idx += 256) {
            int c = idx >> 6, o = idx & 63;
            g_WT1[side*CC*CC + idx] = pw[o*CC + c] * nw[c];
        }
        // rs1 / b1: warp-per-8-outputs shuffle reductions
        for (int j = 0; j < 8; j++) {
            int o = wid * 8 + j;
            float wv0 = pw[o*CC + lane], wv1 = pw[o*CC + lane + 32];
            float rs = wv0*nw[lane] + wv1*nw[lane + 32];
            float bb = wv0*nb[lane] + wv1*nb[lane + 32];
            for (int off = 16; off; off >>= 1) {
                rs += __shfl_down_sync(0xffffffffu, rs, off);
                bb += __shfl_down_sync(0xffffffffu, bb, off);
            }
            if (lane == 0) {
                g_rs1[side*CC + o] = rs;
                g_b1 [side*CC + o] = bb + pb[o];
            }
        }
        return;
    }

    // ======== blocks 0..7: per-(side,b) dynamic-conv folding ========
    const int sb   = bid;
    const int side = sb >> 2, b = sb & 3;
    const float* f1w  = side ? rf1w  : lf1w;
    const float* f1b  = side ? rf1b  : lf1b;
    const float* f2w  = side ? rf2w  : lf2w;
    const float* f2b  = side ? rf2b  : lf2b;
    const float* Wk   = side ? rW    : lW;
    const float* bias = side ? rbias : lbias;
    const float* bg   = side ? gamma : beta;
    const float* p2w  = side ? lp2w  : rp2w;   // out_l path consumes V_r (rp2)!
    const float* p2b  = side ? lp2b  : rp2b;
    const float* gap  = g_gap + side*BB*CC + b*CC;

    // attention2d first layer: 3 warp-parallel dot products
    if (wid < 3) {
        float s = f1w[wid*CC + lane]*gap[lane] + f1w[wid*CC + lane + 32]*gap[lane + 32];
        for (int off = 16; off; off >>= 1) s += __shfl_down_sync(0xffffffffu, s, off);
        if (lane == 0) sA1[wid] = fmaxf(s + f1b[wid], 0.f);
    }
    // stage p2w into smem meanwhile
    for (int idx = tid; idx < CC*CC; idx += 256) sPs[idx] = p2w[idx];
    __syncthreads();

    if (tid == 0) {
        float a2[3];
        #pragma unroll
        for (int k = 0; k < 3; k++) {
            float s = f2b[k];
            #pragma unroll
            for (int j = 0; j < 3; j++) s += f2w[k*3 + j] * sA1[j];
            a2[k] = s;
        }
        float mx = fmaxf(a2[0], fmaxf(a2[1], a2[2]));
        float e0 = expf(a2[0]-mx), e1 = expf(a2[1]-mx), e2 = expf(a2[2]-mx);
        float inv = 1.f / (e0 + e1 + e2);
        sAtt[0] = e0*inv; sAtt[1] = e1*inv; sAtt[2] = e2*inv;
    }
    __syncthreads();

    const float at0 = sAtt[0], at1 = sAtt[1], at2 = sAtt[2];

    // Weff into smem (pitch 65): We[o][i] = (sum_k att_k Wk[o][i]) * bg[i]
    for (int idx = tid; idx < CC*CC; idx += 256) {
        int o = idx >> 6, i = idx & 63;
        float w = (at0*Wk[idx] + at1*Wk[CC*CC + idx] + at2*Wk[2*CC*CC + idx]) * bg[i];
        sWe[o*WEP + i] = w;
    }
    __syncthreads();

    // MT[c][o] = sum_i We[o][i] * p2w[i][c]
    // thread -> (o = tid&63, c block of 16 at c0 = (tid>>6)*16)
    {
        int o  = tid & 63;
        int c0 = (tid >> 6) << 4;
        float4 acc0 = {0,0,0,0}, acc1 = {0,0,0,0}, acc2 = {0,0,0,0}, acc3 = {0,0,0,0};
        #pragma unroll 8
        for (int i = 0; i < CC; i++) {
            float w = sWe[o*WEP + i];
            const float4* pr = reinterpret_cast<const float4*>(sPs + i*CC + c0);
            float4 p0 = pr[0], p1 = pr[1], p2 = pr[2], p3 = pr[3];
            acc0.x += w*p0.x; acc0.y += w*p0.y; acc0.z += w*p0.z; acc0.w += w*p0.w;
            acc1.x += w*p1.x; acc1.y += w*p1.y; acc1.z += w*p1.z; acc1.w += w*p1.w;
            acc2.x += w*p2.x; acc2.y += w*p2.y; acc2.z += w*p2.z; acc2.w += w*p2.w;
            acc3.x += w*p3.x; acc3.y += w*p3.y; acc3.z += w*p3.z; acc3.w += w*p3.w;
        }
        float accs[16] = {acc0.x,acc0.y,acc0.z,acc0.w, acc1.x,acc1.y,acc1.z,acc1.w,
                          acc2.x,acc2.y,acc2.z,acc2.w, acc3.x,acc3.y,acc3.z,acc3.w};
        float* dst = g_MT + sb*CC*CC;
        #pragma unroll
        for (int j = 0; j < 16; j++) dst[(c0 + j)*CC + o] = accs[j];
    }

    // cvec[o] = bagg[o] + sum_i We[o][i]*p2b[i]
    if (tid < CC) {
        int o = tid;
        float s = at0*bias[o] + at1*bias[CC + o] + at2*bias[2*CC + o];
        #pragma unroll 8
        for (int i = 0; i < CC; i++) s += sWe[o*WEP + i] * p2b[i];
        g_cvec[sb*CC + o] = s;
    }
}

// ---------------- fused main kernel ----------------
// One 64x64 @ 64x80 GEMM micro-kernel: threads as 16(oq) x 16(wq); each thread
// computes a 4(o) x 5(w) tile. WTm is [c][o] so the 4 o-values are one float4.
__device__ __forceinline__ void gemm_tile(
    const float* __restrict__ WTm, const float* __restrict__ xs,
    float* __restrict__ os,
    const float* mu, const float* iv,
    const float* __restrict__ rs, const float* __restrict__ b1, int tid)
{
    int oq = tid >> 4, wq = tid & 15;
    int o0 = oq << 2, w0 = wq * 5;
    float acc[4][5];
    #pragma unroll
    for (int i = 0; i < 4; i++)
        #pragma unroll
        for (int j = 0; j < 5; j++) acc[i][j] = 0.f;

    #pragma unroll 8
    for (int c = 0; c < CC; c++) {
        float4 wv = *reinterpret_cast<const float4*>(WTm + (c << 6) + o0);
        const float* xc = xs + c*PIT + w0;
        float x0 = xc[0], x1 = xc[1], x2 = xc[2], x3 = xc[3], x4 = xc[4];
        float wr[4] = {wv.x, wv.y, wv.z, wv.w};
        #pragma unroll
        for (int i = 0; i < 4; i++) {
            acc[i][0] += wr[i]*x0; acc[i][1] += wr[i]*x1; acc[i][2] += wr[i]*x2;
            acc[i][3] += wr[i]*x3; acc[i][4] += wr[i]*x4;
        }
    }
    if (mu) {   // Q epilogue: fold LayerNorm
        #pragma unroll
        for (int i = 0; i < 4; i++) {
            float rsv = rs[o0+i], bv = b1[o0+i];
            #pragma unroll
            for (int j = 0; j < 5; j++) {
                int w = w0 + j;
                os[(o0+i)*PIT + w] = iv[w]*(acc[i][j] - mu[w]*rsv) + bv;
            }
        }
    } else {
        #pragma unroll
        for (int i = 0; i < 4; i++)
            #pragma unroll
            for (int j = 0; j < 5; j++)
                os[(o0+i)*PIT + w0 + j] = acc[i][j];
    }
}

__global__ void __launch_bounds__(256, 2) k_main(
    const float* __restrict__ xl_g, const float* __restrict__ xr_g,
    float* __restrict__ out)
{
    extern __shared__ float sm[];
    float* xls  = sm;
    float* xrs  = sm + 1*CC*PIT;
    float* qa   = sm + 2*CC*PIT;   // Ql then Pr
    float* qb   = sm + 3*CC*PIT;   // Qr then Pl
    float* mul  = sm + 4*CC*PIT;
    float* invl = mul  + WT;
    float* mur  = invl + WT;
    float* invr = mur  + WT;
    float* Ssm  = invr + WT;       // 800
    float* Ar   = Ssm  + NSUB*100; // 800
    float* Al   = Ar   + NSUB*100; // 800

    int gid = blockIdx.x;
    int g   = gid & 3;
    int h   = (gid >> 2) % HH;
    int b   = gid / (4*HH);
    int tid = threadIdx.x;
    size_t base = (size_t)b * (CC*HW) + (size_t)h * WW + (size_t)g * WT;

    // stage 1: load tiles
    for (int idx = tid; idx < CC*WT; idx += 256) {
        int c = idx / WT, w = idx - c*WT;
        size_t go = base + (size_t)c*HW + w;
        xls[c*PIT + w] = xl_g[go];
        xrs[c*PIT + w] = xr_g[go];
    }
    __syncthreads();

    // stage 2: per-column LN stats
    if (tid < 2*WT) {
        int side = tid / WT, w = tid - side*WT;
        const float* xs = side ? xrs : xls;
        float s = 0.f, s2 = 0.f;
        #pragma unroll
        for (int c = 0; c < CC; c++) {
            float v = xs[c*PIT + w];
            s += v; s2 += v*v;
        }
        float mu  = s * (1.f/CC);
        float var = s2 * (1.f/CC) - mu*mu;
        float ivv = rsqrtf(var + EPSV);
        if (side) { mur[w] = mu; invr[w] = ivv; }
        else      { mul[w] = mu; invl[w] = ivv; }
    }
    __syncthreads();

    // stage 3: Q projections (LN folded)
    gemm_tile(g_WT1,        xls, qa, mul, invl, g_rs1,      g_b1,      tid);
    gemm_tile(g_WT1 + CC*CC, xrs, qb, mur, invr, g_rs1 + CC, g_b1 + CC, tid);
    __syncthreads();

    // stage 4: attention scores (2x2 blocks, 200 threads)
    if (tid < 200) {
        int n = tid / 25, r = tid - 25*n;
        int u0 = (r/5)*2, v0 = (r%5)*2;
        const float* A_ = qa + n*10;
        const float* B_ = qb + n*10;
        float a00=0, a01=0, a10=0, a11=0;
        #pragma unroll 8
        for (int o = 0; o < CC; o++) {
            float l0 = A_[o*PIT + u0], l1 = A_[o*PIT + u0 + 1];
            float r0 = B_[o*PIT + v0], r1 = B_[o*PIT + v0 + 1];
            a00 += l0*r0; a01 += l0*r1; a10 += l1*r0; a11 += l1*r1;
        }
        float* Sp = Ssm + n*100;
        const float sc = 0.125f;          // C^-0.5
        Sp[ u0   *10 + v0    ] = a00*sc;
        Sp[ u0   *10 + v0 + 1] = a01*sc;
        Sp[(u0+1)*10 + v0    ] = a10*sc;
        Sp[(u0+1)*10 + v0 + 1] = a11*sc;
    }
    __syncthreads();

    // stage 5: dual softmax (rows -> Ar, cols -> Al)
    if (tid < 80) {
        int n = tid / 10, u = tid - 10*n;
        const float* Sp = Ssm + n*100 + u*10;
        float m = Sp[0];
        #pragma unroll
        for (int v = 1; v < 10; v++) m = fmaxf(m, Sp[v]);
        float e[10], s = 0.f;
        #pragma unroll
        for (int v = 0; v < 10; v++) { e[v] = __expf(Sp[v]-m); s += e[v]; }
        float inv = 1.f/s;
        float* dst = Ar + n*100 + u*10;
        #pragma unroll
        for (int v = 0; v < 10; v++) dst[v] = e[v]*inv;
    } else if (tid < 160) {
        int t = tid - 80;
        int n = t / 10, v = t - 10*n;
        const float* Sp = Ssm + n*100 + v;
        float m = Sp[0];
        #pragma unroll
        for (int u = 1; u < 10; u++) m = fmaxf(m, Sp[u*10]);
        float e[10], s = 0.f;
        #pragma unroll
        for (int u = 0; u < 10; u++) { e[u] = __expf(Sp[u*10]-m); s += e[u]; }
        float inv = 1.f/s;
        float* dst = Al + n*100 + v;
        #pragma unroll
        for (int u = 0; u < 10; u++) dst[u*10] = e[u]*inv;
    }
    __syncthreads();

    // stage 6: P projections (dynamic-conv matrices pre-folded)
    gemm_tile(g_MT + (0*BB + b)*CC*CC, xrs, qa, nullptr, nullptr, nullptr, nullptr, tid); // Pr
    gemm_tile(g_MT + (1*BB + b)*CC*CC, xls, qb, nullptr, nullptr, nullptr, nullptr, tid); // Pl
    __syncthreads();

    // stage 7: aggregate + residual, in place into xls/xrs
    {
        int oq = tid >> 4, wq = tid & 15;
        int o0 = oq << 2, w0 = wq * 5;
        int n  = w0 / 10;
        int ub = w0 - n*10;                  // 0 or 5
        const float* Arn = Ar + n*100;
        const float* Aln = Al + n*100;
        #pragma unroll
        for (int i = 0; i < 4; i++) {
            int o = o0 + i;
            float cl = g_cvec[b*CC + o];
            float cr = g_cvec[(BB + b)*CC + o];
            float pr[10], pl[10];
            #pragma unroll
            for (int v = 0; v < 10; v++) {
                pr[v] = qa[o*PIT + n*10 + v];
                pl[v] = qb[o*PIT + n*10 + v];
            }
            #pragma unroll
            for (int j = 0; j < 5; j++) {
                int u = ub + j;
                float sl = cl, sr = cr;
                #pragma unroll
                for (int v = 0; v < 10; v++) {
                    sl += Arn[u*10 + v] * pr[v];   // out_l[o,u] = sum_v A_r2l[u,v] Pr[o,v]
                    sr += Aln[v*10 + u] * pl[v];   // out_r[o,u] = sum_uu A_l2r[uu,u] Pl[o,uu]
                }
                xls[o*PIT + w0 + j] += sl;
                xrs[o*PIT + w0 + j] += sr;
            }
        }
    }
    __syncthreads();

    // stage 8: coalesced writeback
    const size_t OUTOFF = (size_t)BB*CC*HW;
    for (int idx = tid; idx < CC*WT; idx += 256) {
        int c = idx / WT, w = idx - c*WT;
        size_t go = base + (size_t)c*HW + w;
        out[go]          = xls[c*PIT + w];
        out[OUTOFF + go] = xrs[c*PIT + w];
    }
}

// ---------------- launch ----------------
extern "C" void kernel_launch(void* const* d_in, const int* in_sizes, int n_in,
                              void* d_out, int out_size) {
    const float* xl    = (const float*)d_in[0];
    const float* xr    = (const float*)d_in[1];
    const float* nlw   = (const float*)d_in[2];
    const float* nlb   = (const float*)d_in[3];
    const float* nrw   = (const float*)d_in[4];
    const float* nrb   = (const float*)d_in[5];
    const float* lp1w  = (const float*)d_in[6];
    const float* lp1b  = (const float*)d_in[7];
    const float* rp1w  = (const float*)d_in[8];
    const float* rp1b  = (const float*)d_in[9];
    const float* lp2w  = (const float*)d_in[10];
    const float* lp2b  = (const float*)d_in[11];
    const float* rp2w  = (const float*)d_in[12];
    const float* rp2b  = (const float*)d_in[13];
    const float* beta  = (const float*)d_in[14];
    const float* gamma = (const float*)d_in[15];
    const float* lf1w  = (const float*)d_in[16];
    const float* lf1b  = (const float*)d_in[17];
    const float* lf2w  = (const float*)d_in[18];
    const float* lf2b  = (const float*)d_in[19];
    const float* lW    = (const float*)d_in[20];
    const float* lbias = (const float*)d_in[21];
    const float* rf1w  = (const float*)d_in[22];
    const float* rf1b  = (const float*)d_in[23];
    const float* rf2w  = (const float*)d_in[24];
    const float* rf2b  = (const float*)d_in[25];
    const float* rW    = (const float*)d_in[26];
    const float* rbias = (const float*)d_in[27];
    float* out = (float*)d_out;

    const int SMEM_BYTES = (4*CC*PIT + 4*WT + 3*NSUB*100) * sizeof(float); // 93,824

    cudaFuncSetAttribute(k_main, cudaFuncAttributeMaxDynamicSharedMemorySize, SMEM_BYTES);

    k_gap <<<2*BB*CC, 256>>>(xl, xr);
    k_prep<<<10, 256>>>(lp1w, lp1b, rp1w, rp1b, nlw, nlb, nrw, nrb,
                        lp2w, lp2b, rp2w, rp2b, beta, gamma,
                        lf1w, lf1b, lf2w, lf2b, lW, lbias,
                        rf1w, rf1b, rf2w, rf2b, rW, rbias);
    k_main<<<BB*HH*(WW/WT), 256, SMEM_BYTES>>>(xl, xr, out);
}

// round 8
// speedup vs baseline: 2.2969x; 1.1278x over previous
#include <cuda_runtime.h>

// ---------------- problem constants ----------------
#define BB   4
#define CC   64
#define HH   180
#define WW   320
#define HW   57600          // H*W
#define WT   80             // width tile per CTA (8 sub-chunks of 10)
#define PIT  81             // smem pitch (conflict-free)
#define NSUB 8
#define EPSV 1e-6f
#define GSPLIT 4

// ---------------- device scratch (no allocations allowed) ----------------
__device__ float g_gpart[2*BB*CC*GSPLIT];  // partial sums for gap
__device__ float g_WT1 [2*CC*CC];        // [side][c][o]  p1_w * norm_w, transposed
__device__ float g_b1  [2*CC];
__device__ float g_rs1 [2*CC];
__device__ float g_MT  [2*BB*CC*CC];     // [side*4+b][c][o]  (Weff @ p2_w)^T
__device__ float g_cvec[2*BB*CC];        // Weff@p2_b + bagg
__device__ float g_G   [CC*CC];          // [c'][c] : G[c][c'] = sum_o W1l[o,c] W1r[o,c']
__device__ float g_vec [4*CC];           // vA, vB, vC, vD
__device__ float g_scal[4];              // srr, srb, sbr, sbb

// ---------------- prepass 1: global average pool (partials) ----------------
__global__ void k_gap(const float* __restrict__ xl, const float* __restrict__ xr) {
    int blk = blockIdx.x;                        // 0..2047
    int id = blk >> 2, q = blk & 3;
    const float* x = (id < BB*CC) ? xl : xr;
    int rem = id & (BB*CC - 1);
    const float4* p = reinterpret_cast<const float4*>(
        x + (size_t)rem * HW + (size_t)q * (HW/GSPLIT));
    float s = 0.f;
    for (int i = threadIdx.x; i < HW/(4*GSPLIT); i += blockDim.x) {
        float4 v = p[i];
        s += (v.x + v.y) + (v.z + v.w);
    }
    __shared__ float red[8];
    for (int o = 16; o; o >>= 1) s += __shfl_down_sync(0xffffffffu, s, o);
    if ((threadIdx.x & 31) == 0) red[threadIdx.x >> 5] = s;
    __syncthreads();
    if (threadIdx.x < 8) {
        s = red[threadIdx.x];
        for (int o = 4; o; o >>= 1) s += __shfl_down_sync(0xffu, s, o);
        if (threadIdx.x == 0) g_gpart[id*GSPLIT + q] = s;   // raw sum
    }
}

// ---------------- prepass 2: fold weights + dynamic conv ----------------
// grid = 10 blocks x 256 threads.
//   blocks 0..7  : sb = side*4+b  -> att mixture, Weff (smem), MT = Weff@p2w, cvec
//   blocks 8..9  : side = bid-8   -> LN fold into Q projection (WT1, b1, rs1)
#define WEP 65   // smem pitch (bank-conflict-free column reads)

__global__ void __launch_bounds__(256) k_prep(
    const float* __restrict__ lp1w, const float* __restrict__ lp1b,
    const float* __restrict__ rp1w, const float* __restrict__ rp1b,
    const float* __restrict__ nlw,  const float* __restrict__ nlb,
    const float* __restrict__ nrw,  const float* __restrict__ nrb,
    const float* __restrict__ lp2w, const float* __restrict__ lp2b,
    const float* __restrict__ rp2w, const float* __restrict__ rp2b,
    const float* __restrict__ beta, const float* __restrict__ gamma,
    const float* __restrict__ lf1w, const float* __restrict__ lf1b,
    const float* __restrict__ lf2w, const float* __restrict__ lf2b,
    const float* __restrict__ lW,   const float* __restrict__ lbias,
    const float* __restrict__ rf1w, const float* __restrict__ rf1b,
    const float* __restrict__ rf2w, const float* __restrict__ rf2b,
    const float* __restrict__ rW,   const float* __restrict__ rbias)
{
    __shared__ float sWe[CC*WEP];    // Weff, pitch 65
    __shared__ float sPs[CC*CC];     // p2w staged
    __shared__ float sA1[3];
    __shared__ float sAtt[3];

    const int tid  = threadIdx.x;
    const int lane = tid & 31;
    const int wid  = tid >> 5;
    const int bid  = blockIdx.x;

    // ======== blocks 8,9: LN fold ========
    if (bid >= 8) {
        int side = bid - 8;
        const float* pw = side ? rp1w : lp1w;
        const float* pb = side ? rp1b : lp1b;
        const float* nw = side ? nrw  : nlw;
        const float* nb = side ? nrb  : nlb;

        for (int idx = tid; idx < CC*CC; idx += 256) {
            int c = idx >> 6, o = idx & 63;
            g_WT1[side*CC*CC + idx] = pw[o*CC + c] * nw[c];
        }
        for (int j = 0; j < 8; j++) {
            int o = wid * 8 + j;
            float wv0 = pw[o*CC + lane], wv1 = pw[o*CC + lane + 32];
            float rs = wv0*nw[lane] + wv1*nw[lane + 32];
            float bb = wv0*nb[lane] + wv1*nb[lane + 32];
            for (int off = 16; off; off >>= 1) {
                rs += __shfl_down_sync(0xffffffffu, rs, off);
                bb += __shfl_down_sync(0xffffffffu, bb, off);
            }
            if (lane == 0) {
                g_rs1[side*CC + o] = rs;
                g_b1 [side*CC + o] = bb + pb[o];
            }
        }
        return;
    }

    // ======== blocks 0..7: per-(side,b) dynamic-conv folding ========
    const int sb   = bid;
    const int side = sb >> 2, b = sb & 3;
    const float* f1w  = side ? rf1w  : lf1w;
    const float* f1b  = side ? rf1b  : lf1b;
    const float* f2w  = side ? rf2w  : lf2w;
    const float* f2b  = side ? rf2b  : lf2b;
    const float* Wk   = side ? rW    : lW;
    const float* bias = side ? rbias : lbias;
    const float* bg   = side ? gamma : beta;
    const float* p2w  = side ? lp2w  : rp2w;   // out_l path consumes V_r (rp2)!
    const float* p2b  = side ? lp2b  : rp2b;

    // attention2d first layer: 3 warp-parallel dot products (gap from partials)
    if (wid < 3) {
        int base4 = (side*BB*CC + b*CC) * GSPLIT;
        int i0 = base4 + lane*GSPLIT, i1 = base4 + (lane+32)*GSPLIT;
        float g0 = (g_gpart[i0]+g_gpart[i0+1]+g_gpart[i0+2]+g_gpart[i0+3]) * (1.f/HW);
        float g1 = (g_gpart[i1]+g_gpart[i1+1]+g_gpart[i1+2]+g_gpart[i1+3]) * (1.f/HW);
        float s = f1w[wid*CC + lane]*g0 + f1w[wid*CC + lane + 32]*g1;
        for (int off = 16; off; off >>= 1) s += __shfl_down_sync(0xffffffffu, s, off);
        if (lane == 0) sA1[wid] = fmaxf(s + f1b[wid], 0.f);
    }
    for (int idx = tid; idx < CC*CC; idx += 256) sPs[idx] = p2w[idx];
    __syncthreads();

    if (tid == 0) {
        float a2[3];
        #pragma unroll
        for (int k = 0; k < 3; k++) {
            float s = f2b[k];
            #pragma unroll
            for (int j = 0; j < 3; j++) s += f2w[k*3 + j] * sA1[j];
            a2[k] = s;
        }
        float mx = fmaxf(a2[0], fmaxf(a2[1], a2[2]));
        float e0 = expf(a2[0]-mx), e1 = expf(a2[1]-mx), e2 = expf(a2[2]-mx);
        float inv = 1.f / (e0 + e1 + e2);
        sAtt[0] = e0*inv; sAtt[1] = e1*inv; sAtt[2] = e2*inv;
    }
    __syncthreads();

    const float at0 = sAtt[0], at1 = sAtt[1], at2 = sAtt[2];

    for (int idx = tid; idx < CC*CC; idx += 256) {
        int o = idx >> 6, i = idx & 63;
        float w = (at0*Wk[idx] + at1*Wk[CC*CC + idx] + at2*Wk[2*CC*CC + idx]) * bg[i];
        sWe[o*WEP + i] = w;
    }
    __syncthreads();

    // MT[c][o] = sum_i We[o][i] * p2w[i][c]
    {
        int o  = tid & 63;
        int c0 = (tid >> 6) << 4;
        float4 acc0 = {0,0,0,0}, acc1 = {0,0,0,0}, acc2 = {0,0,0,0}, acc3 = {0,0,0,0};
        #pragma unroll 8
        for (int i = 0; i < CC; i++) {
            float w = sWe[o*WEP + i];
            const float4* pr = reinterpret_cast<const float4*>(sPs + i*CC + c0);
            float4 p0 = pr[0], p1 = pr[1], p2 = pr[2], p3 = pr[3];
            acc0.x += w*p0.x; acc0.y += w*p0.y; acc0.z += w*p0.z; acc0.w += w*p0.w;
            acc1.x += w*p1.x; acc1.y += w*p1.y; acc1.z += w*p1.z; acc1.w += w*p1.w;
            acc2.x += w*p2.x; acc2.y += w*p2.y; acc2.z += w*p2.z; acc2.w += w*p2.w;
            acc3.x += w*p3.x; acc3.y += w*p3.y; acc3.z += w*p3.z; acc3.w += w*p3.w;
        }
        float accs[16] = {acc0.x,acc0.y,acc0.z,acc0.w, acc1.x,acc1.y,acc1.z,acc1.w,
                          acc2.x,acc2.y,acc2.z,acc2.w, acc3.x,acc3.y,acc3.z,acc3.w};
        float* dst = g_MT + sb*CC*CC;
        #pragma unroll
        for (int j = 0; j < 16; j++) dst[(c0 + j)*CC + o] = accs[j];
    }

    if (tid < CC) {
        int o = tid;
        float s = at0*bias[o] + at1*bias[CC + o] + at2*bias[2*CC + o];
        #pragma unroll 8
        for (int i = 0; i < CC; i++) s += sWe[o*WEP + i] * p2b[i];
        g_cvec[sb*CC + o] = s;
    }
}

// ---------------- prepass 3: G matrix + correction vectors/scalars ----------------
// grid = 5 blocks x 256 threads. blocks 0..3: G rows; block 4: vectors + scalars.
__global__ void __launch_bounds__(256) k_prep2() {
    __shared__ float sWl[CC*WEP];
    __shared__ float sWr[CC*WEP];
    const int tid = threadIdx.x, bid = blockIdx.x;
    for (int idx = tid; idx < CC*CC; idx += 256) {
        int c = idx >> 6, o = idx & 63;
        sWl[c*WEP + o] = g_WT1[idx];
        sWr[c*WEP + o] = g_WT1[CC*CC + idx];
    }
    __syncthreads();

    if (bid < 4) {
        // g_G[c'][c] = sum_o Wl[c][o] * Wr[c'][o]
        int c   = tid & 63;
        int cp0 = bid*16 + (tid >> 6)*4;
        float a0=0,a1=0,a2=0,a3=0;
        #pragma unroll 8
        for (int o = 0; o < CC; o++) {
            float wl = sWl[c*WEP + o];
            a0 += wl * sWr[(cp0+0)*WEP + o];
            a1 += wl * sWr[(cp0+1)*WEP + o];
            a2 += wl * sWr[(cp0+2)*WEP + o];
            a3 += wl * sWr[(cp0+3)*WEP + o];
        }
        g_G[(cp0+0)*CC + c] = a0;
        g_G[(cp0+1)*CC + c] = a1;
        g_G[(cp0+2)*CC + c] = a2;
        g_G[(cp0+3)*CC + c] = a3;
    } else {
        __shared__ float sr[4*CC];   // rsl, rsr, b1l, b1r
        if (tid < 64) {
            sr[tid]       = g_rs1[tid];
            sr[64 + tid]  = g_rs1[CC + tid];
            sr[128 + tid] = g_b1[tid];
            sr[192 + tid] = g_b1[CC + tid];
        }
        __syncthreads();
        if (tid < 64) {
            int c = tid;
            float vA=0,vB=0,vC=0,vD=0;
            #pragma unroll 8
            for (int o = 0; o < CC; o++) {
                float wl = sWl[c*WEP + o], wr = sWr[c*WEP + o];
                vA += wl * sr[64 + o];    // W1l^T rs_r
                vB += wl * sr[192 + o];   // W1l^T b1_r
                vC += wr * sr[o];         // W1r^T rs_l
                vD += wr * sr[128 + o];   // W1r^T b1_l
            }
            g_vec[c] = vA; g_vec[64+c] = vB; g_vec[128+c] = vC; g_vec[192+c] = vD;
        }
        int wid = tid >> 5, lane = tid & 31;
        if (wid < 4) {
            const float *x1, *x2;
            if      (wid == 0) { x1 = sr;       x2 = sr + 64;  }  // srr
            else if (wid == 1) { x1 = sr;       x2 = sr + 192; }  // srb
            else if (wid == 2) { x1 = sr + 128; x2 = sr + 64;  }  // sbr
            else               { x1 = sr + 128; x2 = sr + 192; }  // sbb
            float s = x1[lane]*x2[lane] + x1[lane+32]*x2[lane+32];
            for (int off = 16; off; off >>= 1) s += __shfl_down_sync(0xffffffffu, s, off);
            if (lane == 0) g_scal[wid] = s;
        }
    }
}

// ---------------- fused main kernel ----------------
// One 64x64 @ 64x80 GEMM micro-kernel: threads as 16(oq) x 16(wq); each thread
// computes a 4(o) x 5(w) tile. WTm is [inner][out] so the 4 out-values are one float4.
__device__ __forceinline__ void gemm_tile(
    const float* __restrict__ WTm, const float* __restrict__ xs,
    float* __restrict__ os, int tid)
{
    int oq = tid >> 4, wq = tid & 15;
    int o0 = oq << 2, w0 = wq * 5;
    float acc[4][5];
    #pragma unroll
    for (int i = 0; i < 4; i++)
        #pragma unroll
        for (int j = 0; j < 5; j++) acc[i][j] = 0.f;

    #pragma unroll 8
    for (int c = 0; c < CC; c++) {
        float4 wv = *reinterpret_cast<const float4*>(WTm + (c << 6) + o0);
        const float* xc = xs + c*PIT + w0;
        float x0 = xc[0], x1 = xc[1], x2 = xc[2], x3 = xc[3], x4 = xc[4];
        float wr[4] = {wv.x, wv.y, wv.z, wv.w};
        #pragma unroll
        for (int i = 0; i < 4; i++) {
            acc[i][0] += wr[i]*x0; acc[i][1] += wr[i]*x1; acc[i][2] += wr[i]*x2;
            acc[i][3] += wr[i]*x3; acc[i][4] += wr[i]*x4;
        }
    }
    #pragma unroll
    for (int i = 0; i < 4; i++)
        #pragma unroll
        for (int j = 0; j < 5; j++)
            os[(o0+i)*PIT + w0 + j] = acc[i][j];
}

__global__ void __launch_bounds__(256, 2) k_main(
    const float* __restrict__ xl_g, const float* __restrict__ xr_g,
    float* __restrict__ out)
{
    extern __shared__ float sm[];
    float* xls  = sm;
    float* xrs  = sm + 1*CC*PIT;
    float* qa   = sm + 2*CC*PIT;   // Z then Pr
    float* qb   = sm + 3*CC*PIT;   // Pl
    float* muls = sm + 4*CC*PIT;
    float* invl = muls + WT;
    float* murs = invl + WT;
    float* invr = murs + WT;
    float* Ssm  = invr + WT;       // 800
    float* Ar   = Ssm  + NSUB*100; // 800
    float* Al   = Ar   + NSUB*100; // 800
    float* svec = Al   + NSUB*100; // 256 (vA,vB,vC,vD)
    float* sdA  = svec + 4*CC;     // 80
    float* sdB  = sdA + WT;
    float* sdC  = sdB + WT;
    float* sdD  = sdC + WT;

    int gid = blockIdx.x;
    int g   = gid & 3;
    int h   = (gid >> 2) % HH;
    int b   = gid / (4*HH);
    int tid = threadIdx.x;
    size_t base = (size_t)b * (CC*HW) + (size_t)h * WW + (size_t)g * WT;

    // stage 1: load tiles + correction vectors
    svec[tid] = g_vec[tid];
    for (int idx = tid; idx < CC*WT; idx += 256) {
        int c = idx / WT, w = idx - c*WT;
        size_t go = base + (size_t)c*HW + w;
        xls[c*PIT + w] = xl_g[go];
        xrs[c*PIT + w] = xr_g[go];
    }
    __syncthreads();

    // stage 2: per-column LN stats + correction dots (tid<160),
    // overlapped with stage 3: Z = G @ xr (all threads)
    if (tid < 2*WT) {
        int side = tid / WT, w = tid - side*WT;
        const float* xs = side ? xrs : xls;
        const float* v0 = svec + side*128;
        float s = 0.f, s2 = 0.f, a0 = 0.f, a1 = 0.f;
        #pragma unroll
        for (int c = 0; c < CC; c++) {
            float v = xs[c*PIT + w];
            s += v; s2 += v*v;
            a0 += v0[c]      * v;
            a1 += v0[64 + c] * v;
        }
        float mu  = s * (1.f/CC);
        float var = s2 * (1.f/CC) - mu*mu;
        float ivv = rsqrtf(var + EPSV);
        if (side) { murs[w] = mu; invr[w] = ivv; sdC[w] = a0; sdD[w] = a1; }
        else      { muls[w] = mu; invl[w] = ivv; sdA[w] = a0; sdB[w] = a1; }
    }
    gemm_tile(g_G, xrs, qa, tid);    // Z[c][v] = sum_c' G[c][c'] xr[c'][v]
    __syncthreads();

    // stage 4: attention scores via S0 = xl^T Z + rank-1 LN corrections
    if (tid < 200) {
        int n = tid / 25, r = tid - 25*n;
        int u0 = (r/5)*2, v0 = (r%5)*2;
        const float* A_ = xls + n*10;
        const float* B_ = qa  + n*10;
        float a00=0, a01=0, a10=0, a11=0;
        #pragma unroll 8
        for (int c = 0; c < CC; c++) {
            float l0 = A_[c*PIT + u0], l1 = A_[c*PIT + u0 + 1];
            float r0 = B_[c*PIT + v0], r1 = B_[c*PIT + v0 + 1];
            a00 += l0*r0; a01 += l0*r1; a10 += l1*r0; a11 += l1*r1;
        }
        int wu = n*10 + u0, wv = n*10 + v0;
        float il0 = invl[wu],   il1 = invl[wu+1];
        float ml0 = il0*muls[wu], ml1 = il1*muls[wu+1];
        float dA0 = sdA[wu], dA1 = sdA[wu+1];
        float dB0 = sdB[wu], dB1 = sdB[wu+1];
        float ir0 = invr[wv],   ir1 = invr[wv+1];
        float mr0 = ir0*murs[wv], mr1 = ir1*murs[wv+1];
        float dC0 = sdC[wv], dC1 = sdC[wv+1];
        float dD0 = sdD[wv], dD1 = sdD[wv+1];
        float srr = g_scal[0], srb = g_scal[1], sbr = g_scal[2], sbb = g_scal[3];
        const float sc = 0.125f;          // C^-0.5

        float* Sp = Ssm + n*100;
        Sp[ u0   *10 + v0    ] = sc * (il0*ir0*a00 + il0*dB0 - il0*mr0*dA0
                                       + ir0*dD0 - ir0*ml0*dC0
                                       + ml0*mr0*srr - ml0*srb - mr0*sbr + sbb);
        Sp[ u0   *10 + v0 + 1] = sc * (il0*ir1*a01 + il0*dB0 - il0*mr1*dA0
                                       + ir1*dD1 - ir1*ml0*dC1
                                       + ml0*mr1*srr - ml0*srb - mr1*sbr + sbb);
        Sp[(u0+1)*10 + v0    ] = sc * (il1*ir0*a10 + il1*dB1 - il1*mr0*dA1
                                       + ir0*dD0 - ir0*ml1*dC0
                                       + ml1*mr0*srr - ml1*srb - mr0*sbr + sbb);
        Sp[(u0+1)*10 + v0 + 1] = sc * (il1*ir1*a11 + il1*dB1 - il1*mr1*dA1
                                       + ir1*dD1 - ir1*ml1*dC1
                                       + ml1*mr1*srr - ml1*srb - mr1*sbr + sbb);
    }
    __syncthreads();

    // stage 5: dual softmax (rows -> Ar, cols -> Al)
    if (tid < 80) {
        int n = tid / 10, u = tid - 10*n;
        const float* Sp = Ssm + n*100 + u*10;
        float m = Sp[0];
        #pragma unroll
        for (int v = 1; v < 10; v++) m = fmaxf(m, Sp[v]);
        float e[10], s = 0.f;
        #pragma unroll
        for (int v = 0; v < 10; v++) { e[v] = __expf(Sp[v]-m); s += e[v]; }
        float inv = 1.f/s;
        float* dst = Ar + n*100 + u*10;
        #pragma unroll
        for (int v = 0; v < 10; v++) dst[v] = e[v]*inv;
    } else if (tid < 160) {
        int t = tid - 80;
        int n = t / 10, v = t - 10*n;
        const float* Sp = Ssm + n*100 + v;
        float m = Sp[0];
        #pragma unroll
        for (int u = 1; u < 10; u++) m = fmaxf(m, Sp[u*10]);
        float e[10], s = 0.f;
        #pragma unroll
        for (int u = 0; u < 10; u++) { e[u] = __expf(Sp[u*10]-m); s += e[u]; }
        float inv = 1.f/s;
        float* dst = Al + n*100 + v;
        #pragma unroll
        for (int u = 0; u < 10; u++) dst[u*10] = e[u]*inv;
    }
    __syncthreads();

    // stage 6: P projections (dynamic-conv matrices pre-folded)
    gemm_tile(g_MT + (0*BB + b)*CC*CC, xrs, qa, tid); // Pr
    gemm_tile(g_MT + (1*BB + b)*CC*CC, xls, qb, tid); // Pl
    __syncthreads();

    // stage 7: aggregate + residual, in place into xls/xrs
    {
        int oq = tid >> 4, wq = tid & 15;
        int o0 = oq << 2, w0 = wq * 5;
        int n  = w0 / 10;
        int ub = w0 - n*10;                  // 0 or 5
        const float* Arn = Ar + n*100;
        const float* Aln = Al + n*100;
        #pragma unroll
        for (int i = 0; i < 4; i++) {
            int o = o0 + i;
            float cl = g_cvec[b*CC + o];
            float cr = g_cvec[(BB + b)*CC + o];
            float pr[10], pl[10];
            #pragma unroll
            for (int v = 0; v < 10; v++) {
                pr[v] = qa[o*PIT + n*10 + v];
                pl[v] = qb[o*PIT + n*10 + v];
            }
            #pragma unroll
            for (int j = 0; j < 5; j++) {
                int u = ub + j;
                float sl = cl, sr = cr;
                #pragma unroll
                for (int v = 0; v < 10; v++) {
                    sl += Arn[u*10 + v] * pr[v];   // out_l[o,u] = sum_v A_r2l[u,v] Pr[o,v]
                    sr += Aln[v*10 + u] * pl[v];   // out_r[o,u] = sum_uu A_l2r[uu,u] Pl[o,uu]
                }
                xls[o*PIT + w0 + j] += sl;
                xrs[o*PIT + w0 + j] += sr;
            }
        }
    }
    __syncthreads();

    // stage 8: coalesced writeback
    const size_t OUTOFF = (size_t)BB*CC*HW;
    for (int idx = tid; idx < CC*WT; idx += 256) {
        int c = idx / WT, w = idx - c*WT;
        size_t go = base + (size_t)c*HW + w;
        out[go]          = xls[c*PIT + w];
        out[OUTOFF + go] = xrs[c*PIT + w];
    }
}

// ---------------- launch ----------------
extern "C" void kernel_launch(void* const* d_in, const int* in_sizes, int n_in,
                              void* d_out, int out_size) {
    const float* xl    = (const float*)d_in[0];
    const float* xr    = (const float*)d_in[1];
    const float* nlw   = (const float*)d_in[2];
    const float* nlb   = (const float*)d_in[3];
    const float* nrw   = (const float*)d_in[4];
    const float* nrb   = (const float*)d_in[5];
    const float* lp1w  = (const float*)d_in[6];
    const float* lp1b  = (const float*)d_in[7];
    const float* rp1w  = (const float*)d_in[8];
    const float* rp1b  = (const float*)d_in[9];
    const float* lp2w  = (const float*)d_in[10];
    const float* lp2b  = (const float*)d_in[11];
    const float* rp2w  = (const float*)d_in[12];
    const float* rp2b  = (const float*)d_in[13];
    const float* beta  = (const float*)d_in[14];
    const float* gamma = (const float*)d_in[15];
    const float* lf1w  = (const float*)d_in[16];
    const float* lf1b  = (const float*)d_in[17];
    const float* lf2w  = (const float*)d_in[18];
    const float* lf2b  = (const float*)d_in[19];
    const float* lW    = (const float*)d_in[20];
    const float* lbias = (const float*)d_in[21];
    const float* rf1w  = (const float*)d_in[22];
    const float* rf1b  = (const float*)d_in[23];
    const float* rf2w  = (const float*)d_in[24];
    const float* rf2b  = (const float*)d_in[25];
    const float* rW    = (const float*)d_in[26];
    const float* rbias = (const float*)d_in[27];
    float* out = (float*)d_out;

    const int SMEM_BYTES = (4*CC*PIT + 4*WT + 3*NSUB*100 + 4*CC + 4*WT) * sizeof(float); // 96,128

    cudaFuncSetAttribute(k_main, cudaFuncAttributeMaxDynamicSharedMemorySize, SMEM_BYTES);

    k_gap <<<2*BB*CC*GSPLIT, 256>>>(xl, xr);
    k_prep<<<10, 256>>>(lp1w, lp1b, rp1w, rp1b, nlw, nlb, nrw, nrb,
                        lp2w, lp2b, rp2w, rp2b, beta, gamma,
                        lf1w, lf1b, lf2w, lf2b, lW, lbias,
                        rf1w, rf1b, rf2w, rf2b, rW, rbias);
    k_prep2<<<5, 256>>>();
    k_main<<<BB*HH*(WW/WT), 256, SMEM_BYTES>>>(xl, xr, out);
}

// round 12
// speedup vs baseline: 2.7637x; 1.2032x over previous
#include <cuda_runtime.h>

// ---------------- problem constants ----------------
#define BB   4
#define CC   64
#define HH   180
#define WW   320
#define HW   57600          // H*W
#define WT   80             // width tile per CTA (8 sub-chunks of 10)
#define PIT  84             // smem pitch (multiple of 4 for float4 LDS)
#define NSUB 8
#define EPSV 1e-6f
#define GSPLIT 4
#define NTHR 320

// ---------------- device scratch (no allocations allowed) ----------------
__device__ float g_gpart[2*BB*CC*GSPLIT];  // partial sums for gap
__device__ float g_WT1 [2*CC*CC];        // [side][c][o]  p1_w * norm_w, transposed
__device__ float g_b1  [2*CC];
__device__ float g_rs1 [2*CC];
__device__ float g_MT  [2*BB*CC*CC];     // [side*4+b][c][o]  (Weff @ p2_w)^T
__device__ float g_cvec[2*BB*CC];        // Weff@p2_b + bagg
__device__ float g_G   [CC*CC];          // [c'][c] : G[c][c'] = sum_o W1l[o,c] W1r[o,c']
__device__ float g_vec [4*CC];           // vA, vB, vC, vD
__device__ float g_scal[4];              // srr, srb, sbr, sbb

// ---------------- prepass 1: global average pool (partials) ----------------
__global__ void k_gap(const float* __restrict__ xl, const float* __restrict__ xr) {
    int blk = blockIdx.x;                        // 0..2047
    int id = blk >> 2, q = blk & 3;
    const float* x = (id < BB*CC) ? xl : xr;
    int rem = id & (BB*CC - 1);
    const float4* p = reinterpret_cast<const float4*>(
        x + (size_t)rem * HW + (size_t)q * (HW/GSPLIT));
    float s = 0.f;
    for (int i = threadIdx.x; i < HW/(4*GSPLIT); i += blockDim.x) {
        float4 v = p[i];
        s += (v.x + v.y) + (v.z + v.w);
    }
    __shared__ float red[8];
    for (int o = 16; o; o >>= 1) s += __shfl_down_sync(0xffffffffu, s, o);
    if ((threadIdx.x & 31) == 0) red[threadIdx.x >> 5] = s;
    __syncthreads();
    if (threadIdx.x < 8) {
        s = red[threadIdx.x];
        for (int o = 4; o; o >>= 1) s += __shfl_down_sync(0xffu, s, o);
        if (threadIdx.x == 0) g_gpart[id*GSPLIT + q] = s;   // raw sum
    }
}

// ---------------- prepass 2: fold weights + dynamic conv ----------------
#define WEP 65   // smem pitch (bank-conflict-free column reads)

__global__ void __launch_bounds__(256) k_prep(
    const float* __restrict__ lp1w, const float* __restrict__ lp1b,
    const float* __restrict__ rp1w, const float* __restrict__ rp1b,
    const float* __restrict__ nlw,  const float* __restrict__ nlb,
    const float* __restrict__ nrw,  const float* __restrict__ nrb,
    const float* __restrict__ lp2w, const float* __restrict__ lp2b,
    const float* __restrict__ rp2w, const float* __restrict__ rp2b,
    const float* __restrict__ beta, const float* __restrict__ gamma,
    const float* __restrict__ lf1w, const float* __restrict__ lf1b,
    const float* __restrict__ lf2w, const float* __restrict__ lf2b,
    const float* __restrict__ lW,   const float* __restrict__ lbias,
    const float* __restrict__ rf1w, const float* __restrict__ rf1b,
    const float* __restrict__ rf2w, const float* __restrict__ rf2b,
    const float* __restrict__ rW,   const float* __restrict__ rbias)
{
    __shared__ float sWe[CC*WEP];    // Weff, pitch 65
    __shared__ float sPs[CC*CC];     // p2w staged
    __shared__ float sA1[3];
    __shared__ float sAtt[3];

    const int tid  = threadIdx.x;
    const int lane = tid & 31;
    const int wid  = tid >> 5;
    const int bid  = blockIdx.x;

    // ======== blocks 8,9: LN fold ========
    if (bid >= 8) {
        int side = bid - 8;
        const float* pw = side ? rp1w : lp1w;
        const float* pb = side ? rp1b : lp1b;
        const float* nw = side ? nrw  : nlw;
        const float* nb = side ? nrb  : nlb;

        for (int idx = tid; idx < CC*CC; idx += 256) {
            int c = idx >> 6, o = idx & 63;
            g_WT1[side*CC*CC + idx] = pw[o*CC + c] * nw[c];
        }
        for (int j = 0; j < 8; j++) {
            int o = wid * 8 + j;
            float wv0 = pw[o*CC + lane], wv1 = pw[o*CC + lane + 32];
            float rs = wv0*nw[lane] + wv1*nw[lane + 32];
            float bb = wv0*nb[lane] + wv1*nb[lane + 32];
            for (int off = 16; off; off >>= 1) {
                rs += __shfl_down_sync(0xffffffffu, rs, off);
                bb += __shfl_down_sync(0xffffffffu, bb, off);
            }
            if (lane == 0) {
                g_rs1[side*CC + o] = rs;
                g_b1 [side*CC + o] = bb + pb[o];
            }
        }
        return;
    }

    // ======== blocks 0..7: per-(side,b) dynamic-conv folding ========
    const int sb   = bid;
    const int side = sb >> 2, b = sb & 3;
    const float* f1w  = side ? rf1w  : lf1w;
    const float* f1b  = side ? rf1b  : lf1b;
    const float* f2w  = side ? rf2w  : lf2w;
    const float* f2b  = side ? rf2b  : lf2b;
    const float* Wk   = side ? rW    : lW;
    const float* bias = side ? rbias : lbias;
    const float* bg   = side ? gamma : beta;
    const float* p2w  = side ? lp2w  : rp2w;   // out_l path consumes V_r (rp2)!
    const float* p2b  = side ? lp2b  : rp2b;

    if (wid < 3) {
        int base4 = (side*BB*CC + b*CC) * GSPLIT;
        int i0 = base4 + lane*GSPLIT, i1 = base4 + (lane+32)*GSPLIT;
        float g0 = (g_gpart[i0]+g_gpart[i0+1]+g_gpart[i0+2]+g_gpart[i0+3]) * (1.f/HW);
        float g1 = (g_gpart[i1]+g_gpart[i1+1]+g_gpart[i1+2]+g_gpart[i1+3]) * (1.f/HW);
        float s = f1w[wid*CC + lane]*g0 + f1w[wid*CC + lane + 32]*g1;
        for (int off = 16; off; off >>= 1) s += __shfl_down_sync(0xffffffffu, s, off);
        if (lane == 0) sA1[wid] = fmaxf(s + f1b[wid], 0.f);
    }
    for (int idx = tid; idx < CC*CC; idx += 256) sPs[idx] = p2w[idx];
    __syncthreads();

    if (tid == 0) {
        float a2[3];
        #pragma unroll
        for (int k = 0; k < 3; k++) {
            float s = f2b[k];
            #pragma unroll
            for (int j = 0; j < 3; j++) s += f2w[k*3 + j] * sA1[j];
            a2[k] = s;
        }
        float mx = fmaxf(a2[0], fmaxf(a2[1], a2[2]));
        float e0 = expf(a2[0]-mx), e1 = expf(a2[1]-mx), e2 = expf(a2[2]-mx);
        float inv = 1.f / (e0 + e1 + e2);
        sAtt[0] = e0*inv; sAtt[1] = e1*inv; sAtt[2] = e2*inv;
    }
    __syncthreads();

    const float at0 = sAtt[0], at1 = sAtt[1], at2 = sAtt[2];

    for (int idx = tid; idx < CC*CC; idx += 256) {
        int o = idx >> 6, i = idx & 63;
        float w = (at0*Wk[idx] + at1*Wk[CC*CC + idx] + at2*Wk[2*CC*CC + idx]) * bg[i];
        sWe[o*WEP + i] = w;
    }
    __syncthreads();

    // MT[c][o] = sum_i We[o][i] * p2w[i][c]
    {
        int o  = tid & 63;
        int c0 = (tid >> 6) << 4;
        float4 acc0 = {0,0,0,0}, acc1 = {0,0,0,0}, acc2 = {0,0,0,0}, acc3 = {0,0,0,0};
        #pragma unroll 8
        for (int i = 0; i < CC; i++) {
            float w = sWe[o*WEP + i];
            const float4* pr = reinterpret_cast<const float4*>(sPs + i*CC + c0);
            float4 p0 = pr[0], p1 = pr[1], p2 = pr[2], p3 = pr[3];
            acc0.x += w*p0.x; acc0.y += w*p0.y; acc0.z += w*p0.z; acc0.w += w*p0.w;
            acc1.x += w*p1.x; acc1.y += w*p1.y; acc1.z += w*p1.z; acc1.w += w*p1.w;
            acc2.x += w*p2.x; acc2.y += w*p2.y; acc2.z += w*p2.z; acc2.w += w*p2.w;
            acc3.x += w*p3.x; acc3.y += w*p3.y; acc3.z += w*p3.z; acc3.w += w*p3.w;
        }
        float accs[16] = {acc0.x,acc0.y,acc0.z,acc0.w, acc1.x,acc1.y,acc1.z,acc1.w,
                          acc2.x,acc2.y,acc2.z,acc2.w, acc3.x,acc3.y,acc3.z,acc3.w};
        float* dst = g_MT + sb*CC*CC;
        #pragma unroll
        for (int j = 0; j < 16; j++) dst[(c0 + j)*CC + o] = accs[j];
    }

    if (tid < CC) {
        int o = tid;
        float s = at0*bias[o] + at1*bias[CC + o] + at2*bias[2*CC + o];
        #pragma unroll 8
        for (int i = 0; i < CC; i++) s += sWe[o*WEP + i] * p2b[i];
        g_cvec[sb*CC + o] = s;
    }
}

// ---------------- prepass 3: G matrix + correction vectors/scalars ----------------
__global__ void __launch_bounds__(256) k_prep2() {
    __shared__ float sWl[CC*WEP];
    __shared__ float sWr[CC*WEP];
    const int tid = threadIdx.x, bid = blockIdx.x;
    for (int idx = tid; idx < CC*CC; idx += 256) {
        int c = idx >> 6, o = idx & 63;
        sWl[c*WEP + o] = g_WT1[idx];
        sWr[c*WEP + o] = g_WT1[CC*CC + idx];
    }
    __syncthreads();

    if (bid < 4) {
        int c   = tid & 63;
        int cp0 = bid*16 + (tid >> 6)*4;
        float a0=0,a1=0,a2=0,a3=0;
        #pragma unroll 8
        for (int o = 0; o < CC; o++) {
            float wl = sWl[c*WEP + o];
            a0 += wl * sWr[(cp0+0)*WEP + o];
            a1 += wl * sWr[(cp0+1)*WEP + o];
            a2 += wl * sWr[(cp0+2)*WEP + o];
            a3 += wl * sWr[(cp0+3)*WEP + o];
        }
        g_G[(cp0+0)*CC + c] = a0;
        g_G[(cp0+1)*CC + c] = a1;
        g_G[(cp0+2)*CC + c] = a2;
        g_G[(cp0+3)*CC + c] = a3;
    } else {
        __shared__ float sr[4*CC];   // rsl, rsr, b1l, b1r
        if (tid < 64) {
            sr[tid]       = g_rs1[tid];
            sr[64 + tid]  = g_rs1[CC + tid];
            sr[128 + tid] = g_b1[tid];
            sr[192 + tid] = g_b1[CC + tid];
        }
        __syncthreads();
        if (tid < 64) {
            int c = tid;
            float vA=0,vB=0,vC=0,vD=0;
            #pragma unroll 8
            for (int o = 0; o < CC; o++) {
                float wl = sWl[c*WEP + o], wr = sWr[c*WEP + o];
                vA += wl * sr[64 + o];    // W1l^T rs_r
                vB += wl * sr[192 + o];   // W1l^T b1_r
                vC += wr * sr[o];         // W1r^T rs_l
                vD += wr * sr[128 + o];   // W1r^T b1_l
            }
            g_vec[c] = vA; g_vec[64+c] = vB; g_vec[128+c] = vC; g_vec[192+c] = vD;
        }
        int wid = tid >> 5, lane = tid & 31;
        if (wid < 4) {
            const float *x1, *x2;
            if      (wid == 0) { x1 = sr;       x2 = sr + 64;  }  // srr
            else if (wid == 1) { x1 = sr;       x2 = sr + 192; }  // srb
            else if (wid == 2) { x1 = sr + 128; x2 = sr + 64;  }  // sbr
            else               { x1 = sr + 128; x2 = sr + 192; }  // sbb
            float s = x1[lane]*x2[lane] + x1[lane+32]*x2[lane+32];
            for (int off = 16; off; off >>= 1) s += __shfl_down_sync(0xffffffffu, s, off);
            if (lane == 0) g_scal[wid] = s;
        }
    }
}

// ---------------- fused main kernel ----------------
// GEMM micro-kernel: 320 threads as 16(oq) x 20(wq); each thread computes a
// 4(o) x 4(w) tile. Per c-iter: 1 LDG.128 (weight [c][o]) + 1 LDS.128 (x) + 16 FFMA.
__device__ __forceinline__ void gemm_tile(
    const float* __restrict__ WTm, const float* __restrict__ xs,
    float* __restrict__ os, int tid)
{
    int oq = tid / 20, wq = tid - 20*oq;
    int o0 = oq << 2, w0 = wq << 2;
    float4 a0 = {0,0,0,0}, a1 = {0,0,0,0}, a2 = {0,0,0,0}, a3 = {0,0,0,0};

    #pragma unroll 8
    for (int c = 0; c < CC; c++) {
        float4 wv = *reinterpret_cast<const float4*>(WTm + (c << 6) + o0);
        float4 xv = *reinterpret_cast<const float4*>(xs + c*PIT + w0);
        a0.x += wv.x*xv.x; a0.y += wv.x*xv.y; a0.z += wv.x*xv.z; a0.w += wv.x*xv.w;
        a1.x += wv.y*xv.x; a1.y += wv.y*xv.y; a1.z += wv.y*xv.z; a1.w += wv.y*xv.w;
        a2.x += wv.z*xv.x; a2.y += wv.z*xv.y; a2.z += wv.z*xv.z; a2.w += wv.z*xv.w;
        a3.x += wv.w*xv.x; a3.y += wv.w*xv.y; a3.z += wv.w*xv.z; a3.w += wv.w*xv.w;
    }
    *reinterpret_cast<float4*>(os + (o0+0)*PIT + w0) = a0;
    *reinterpret_cast<float4*>(os + (o0+1)*PIT + w0) = a1;
    *reinterpret_cast<float4*>(os + (o0+2)*PIT + w0) = a2;
    *reinterpret_cast<float4*>(os + (o0+3)*PIT + w0) = a3;
}

__global__ void __launch_bounds__(NTHR, 2) k_main(
    const float* __restrict__ xl_g, const float* __restrict__ xr_g,
    float* __restrict__ out)
{
    extern __shared__ float sm[];
    float* xls  = sm;
    float* xrs  = sm + 1*CC*PIT;
    float* qa   = sm + 2*CC*PIT;   // Z then Pr
    float* qb   = sm + 3*CC*PIT;   // Pl
    float* muls = sm + 4*CC*PIT;
    float* invl = muls + WT;
    float* murs = invl + WT;
    float* invr = murs + WT;
    float* Ssm  = invr + WT;       // 800
    float* Ar   = Ssm  + NSUB*100; // 800
    float* Al   = Ar   + NSUB*100; // 800
    float* svec = Al   + NSUB*100; // 256 (vA,vB,vC,vD)
    float* sdA  = svec + 4*CC;     // 80
    float* sdB  = sdA + WT;
    float* sdC  = sdB + WT;
    float* sdD  = sdC + WT;

    int gid = blockIdx.x;
    int g   = gid & 3;
    int h   = (gid >> 2) % HH;
    int b   = gid / (4*HH);
    int tid = threadIdx.x;
    size_t base = (size_t)b * (CC*HW) + (size_t)h * WW + (size_t)g * WT;

    // stage 1: load tiles (float4) + correction vectors
    if (tid < 4*CC) svec[tid] = g_vec[tid];
    for (int idx = tid; idx < CC*WT/4; idx += NTHR) {
        int c = idx / 20, w4 = idx - c*20;
        size_t go = base + (size_t)c*HW + w4*4;
        float4 vl = *reinterpret_cast<const float4*>(xl_g + go);
        float4 vr = *reinterpret_cast<const float4*>(xr_g + go);
        *reinterpret_cast<float4*>(xls + c*PIT + w4*4) = vl;
        *reinterpret_cast<float4*>(xrs + c*PIT + w4*4) = vr;
    }
    __syncthreads();

    // stage 2: per-column LN stats + correction dots (tid<160),
    // overlapped with stage 3: Z = G @ xr (all threads)
    if (tid < 2*WT) {
        int side = tid / WT, w = tid - side*WT;
        const float* xs = side ? xrs : xls;
        const float* v0 = svec + side*128;
        float s = 0.f, s2 = 0.f, a0 = 0.f, a1 = 0.f;
        #pragma unroll
        for (int c = 0; c < CC; c++) {
            float v = xs[c*PIT + w];
            s += v; s2 += v*v;
            a0 += v0[c]      * v;
            a1 += v0[64 + c] * v;
        }
        float mu  = s * (1.f/CC);
        float var = s2 * (1.f/CC) - mu*mu;
        float ivv = rsqrtf(var + EPSV);
        if (side) { murs[w] = mu; invr[w] = ivv; sdC[w] = a0; sdD[w] = a1; }
        else      { muls[w] = mu; invl[w] = ivv; sdA[w] = a0; sdB[w] = a1; }
    }
    gemm_tile(g_G, xrs, qa, tid);    // Z[c][v] = sum_c' G[c][c'] xr[c'][v]
    __syncthreads();

    // stage 4: attention scores via S0 = xl^T Z + rank-1 LN corrections
    if (tid < 200) {
        int n = tid / 25, r = tid - 25*n;
        int u0 = (r/5)*2, v0 = (r%5)*2;
        const float* A_ = xls + n*10;
        const float* B_ = qa  + n*10;
        float a00=0, a01=0, a10=0, a11=0;
        #pragma unroll 8
        for (int c = 0; c < CC; c++) {
            float l0 = A_[c*PIT + u0], l1 = A_[c*PIT + u0 + 1];
            float r0 = B_[c*PIT + v0], r1 = B_[c*PIT + v0 + 1];
            a00 += l0*r0; a01 += l0*r1; a10 += l1*r0; a11 += l1*r1;
        }
        int wu = n*10 + u0, wv = n*10 + v0;
        float il0 = invl[wu],   il1 = invl[wu+1];
        float ml0 = il0*muls[wu], ml1 = il1*muls[wu+1];
        float dA0 = sdA[wu], dA1 = sdA[wu+1];
        float dB0 = sdB[wu], dB1 = sdB[wu+1];
        float ir0 = invr[wv],   ir1 = invr[wv+1];
        float mr0 = ir0*murs[wv], mr1 = ir1*murs[wv+1];
        float dC0 = sdC[wv], dC1 = sdC[wv+1];
        float dD0 = sdD[wv], dD1 = sdD[wv+1];
        float srr = g_scal[0], srb = g_scal[1], sbr = g_scal[2], sbb = g_scal[3];
        const float sc = 0.125f;          // C^-0.5

        float* Sp = Ssm + n*100;
        Sp[ u0   *10 + v0    ] = sc * (il0*ir0*a00 + il0*dB0 - il0*mr0*dA0
                                       + ir0*dD0 - ir0*ml0*dC0
                                       + ml0*mr0*srr - ml0*srb - mr0*sbr + sbb);
        Sp[ u0   *10 + v0 + 1] = sc * (il0*ir1*a01 + il0*dB0 - il0*mr1*dA0
                                       + ir1*dD1 - ir1*ml0*dC1
                                       + ml0*mr1*srr - ml0*srb - mr1*sbr + sbb);
        Sp[(u0+1)*10 + v0    ] = sc * (il1*ir0*a10 + il1*dB1 - il1*mr0*dA1
                                       + ir0*dD0 - ir0*ml1*dC0
                                       + ml1*mr0*srr - ml1*srb - mr0*sbr + sbb);
        Sp[(u0+1)*10 + v0 + 1] = sc * (il1*ir1*a11 + il1*dB1 - il1*mr1*dA1
                                       + ir1*dD1 - ir1*ml1*dC1
                                       + ml1*mr1*srr - ml1*srb - mr1*sbr + sbb);
    }
    __syncthreads();

    // stage 5: dual softmax (rows -> Ar, cols -> Al)
    if (tid < 80) {
        int n = tid / 10, u = tid - 10*n;
        const float* Sp = Ssm + n*100 + u*10;
        float m = Sp[0];
        #pragma unroll
        for (int v = 1; v < 10; v++) m = fmaxf(m, Sp[v]);
        float e[10], s = 0.f;
        #pragma unroll
        for (int v = 0; v < 10; v++) { e[v] = __expf(Sp[v]-m); s += e[v]; }
        float inv = 1.f/s;
        float* dst = Ar + n*100 + u*10;
        #pragma unroll
        for (int v = 0; v < 10; v++) dst[v] = e[v]*inv;
    } else if (tid < 160) {
        int t = tid - 80;
        int n = t / 10, v = t - 10*n;
        const float* Sp = Ssm + n*100 + v;
        float m = Sp[0];
        #pragma unroll
        for (int u = 1; u < 10; u++) m = fmaxf(m, Sp[u*10]);
        float e[10], s = 0.f;
        #pragma unroll
        for (int u = 0; u < 10; u++) { e[u] = __expf(Sp[u*10]-m); s += e[u]; }
        float inv = 1.f/s;
        float* dst = Al + n*100 + v;
        #pragma unroll
        for (int u = 0; u < 10; u++) dst[u*10] = e[u]*inv;
    }
    __syncthreads();

    // stage 6: P projections (dynamic-conv matrices pre-folded)
    gemm_tile(g_MT + (0*BB + b)*CC*CC, xrs, qa, tid); // Pr
    gemm_tile(g_MT + (1*BB + b)*CC*CC, xls, qb, tid); // Pl
    __syncthreads();

    // stage 7: aggregate + residual, in place into xls/xrs (256 threads, 4o x 5w)
    if (tid < 256) {
        int oq = tid >> 4, wq = tid & 15;
        int o0 = oq << 2, w0 = wq * 5;
        int n  = w0 / 10;
        int ub = w0 - n*10;                  // 0 or 5
        const float* Arn = Ar + n*100;
        const float* Aln = Al + n*100;
        #pragma unroll
        for (int i = 0; i < 4; i++) {
            int o = o0 + i;
            float cl = g_cvec[b*CC + o];
            float cr = g_cvec[(BB + b)*CC + o];
            float pr[10], pl[10];
            #pragma unroll
            for (int v = 0; v < 10; v++) {
                pr[v] = qa[o*PIT + n*10 + v];
                pl[v] = qb[o*PIT + n*10 + v];
            }
            #pragma unroll
            for (int j = 0; j < 5; j++) {
                int u = ub + j;
                float sl = cl, sr = cr;
                #pragma unroll
                for (int v = 0; v < 10; v++) {
                    sl += Arn[u*10 + v] * pr[v];   // out_l[o,u] = sum_v A_r2l[u,v] Pr[o,v]
                    sr += Aln[v*10 + u] * pl[v];   // out_r[o,u] = sum_uu A_l2r[uu,u] Pl[o,uu]
                }
                xls[o*PIT + w0 + j] += sl;
                xrs[o*PIT + w0 + j] += sr;
            }
        }
    }
    __syncthreads();

    // stage 8: coalesced float4 writeback
    const size_t OUTOFF = (size_t)BB*CC*HW;
    for (int idx = tid; idx < CC*WT/4; idx += NTHR) {
        int c = idx / 20, w4 = idx - c*20;
        size_t go = base + (size_t)c*HW + w4*4;
        *reinterpret_cast<float4*>(out + go) =
            *reinterpret_cast<const float4*>(xls + c*PIT + w4*4);
        *reinterpret_cast<float4*>(out + OUTOFF + go) =
            *reinterpret_cast<const float4*>(xrs + c*PIT + w4*4);
    }
}

// ---------------- launch ----------------
extern "C" void kernel_launch(void* const* d_in, const int* in_sizes, int n_in,
                              void* d_out, int out_size) {
    const float* xl    = (const float*)d_in[0];
    const float* xr    = (const float*)d_in[1];
    const float* nlw   = (const float*)d_in[2];
    const float* nlb   = (const float*)d_in[3];
    const float* nrw   = (const float*)d_in[4];
    const float* nrb   = (const float*)d_in[5];
    const float* lp1w  = (const float*)d_in[6];
    const float* lp1b  = (const float*)d_in[7];
    const float* rp1w  = (const float*)d_in[8];
    const float* rp1b  = (const float*)d_in[9];
    const float* lp2w  = (const float*)d_in[10];
    const float* lp2b  = (const float*)d_in[11];
    const float* rp2w  = (const float*)d_in[12];
    const float* rp2b  = (const float*)d_in[13];
    const float* beta  = (const float*)d_in[14];
    const float* gamma = (const float*)d_in[15];
    const float* lf1w  = (const float*)d_in[16];
    const float* lf1b  = (const float*)d_in[17];
    const float* lf2w  = (const float*)d_in[18];
    const float* lf2b  = (const float*)d_in[19];
    const float* lW    = (const float*)d_in[20];
    const float* lbias = (const float*)d_in[21];
    const float* rf1w  = (const float*)d_in[22];
    const float* rf1b  = (const float*)d_in[23];
    const float* rf2w  = (const float*)d_in[24];
    const float* rf2b  = (const float*)d_in[25];
    const float* rW    = (const float*)d_in[26];
    const float* rbias = (const float*)d_in[27];
    float* out = (float*)d_out;

    const int SMEM_BYTES = (4*CC*PIT + 4*WT + 3*NSUB*100 + 4*CC + 4*WT) * sizeof(float); // 99,200

    cudaFuncSetAttribute(k_main, cudaFuncAttributeMaxDynamicSharedMemorySize, SMEM_BYTES);

    k_gap <<<2*BB*CC*GSPLIT, 256>>>(xl, xr);
    k_prep<<<10, 256>>>(lp1w, lp1b, rp1w, rp1b, nlw, nlb, nrw, nrb,
                        lp2w, lp2b, rp2w, rp2b, beta, gamma,
                        lf1w, lf1b, lf2w, lf2b, lW, lbias,
                        rf1w, rf1b, rf2w, rf2b, rW, rbias);
    k_prep2<<<5, 256>>>();
    k_main<<<BB*HH*(WW/WT), NTHR, SMEM_BYTES>>>(xl, xr, out);
}

// round 14
// speedup vs baseline: 2.8657x; 1.0369x over previous
#include <cuda_runtime.h>

// ---------------- problem constants ----------------
#define BB   4
#define CC   64
#define HH   180
#define WW   320
#define HW   57600          // H*W
#define WT   80             // width tile per CTA (8 sub-chunks of 10)
#define PIT  84             // smem pitch (multiple of 4 for float4 LDS)
#define NSUB 8
#define EPSV 1e-6f
#define GSPLIT 4
#define NTHR 320

// ---------------- device scratch (no allocations allowed) ----------------
__device__ float g_gpart[2*BB*CC*GSPLIT];  // partial sums for gap
__device__ float g_WT1 [2*CC*CC];        // [side][c][o]  p1_w * norm_w, transposed
__device__ float g_b1  [2*CC];
__device__ float g_rs1 [2*CC];
__device__ float g_MT  [2*BB*CC*CC];     // [side*4+b][c][o]  (Weff @ p2_w)^T
__device__ float g_cvec[2*BB*CC];        // Weff@p2_b + bagg
__device__ float g_G   [CC*CC];          // [c'][c] : G[c][c'] = sum_o W1l[o,c] W1r[o,c']
__device__ float g_vec [4*CC];           // vA, vB, vC, vD
__device__ float g_scal[4];              // srr, srb, sbr, sbb

// ---------------- prepass 1: global average pool (partials) ----------------
__global__ void k_gap(const float* __restrict__ xl, const float* __restrict__ xr) {
    int blk = blockIdx.x;                        // 0..2047
    int id = blk >> 2, q = blk & 3;
    const float* x = (id < BB*CC) ? xl : xr;
    int rem = id & (BB*CC - 1);
    const float4* p = reinterpret_cast<const float4*>(
        x + (size_t)rem * HW + (size_t)q * (HW/GSPLIT));
    float s = 0.f;
    for (int i = threadIdx.x; i < HW/(4*GSPLIT); i += blockDim.x) {
        float4 v = p[i];
        s += (v.x + v.y) + (v.z + v.w);
    }
    __shared__ float red[8];
    for (int o = 16; o; o >>= 1) s += __shfl_down_sync(0xffffffffu, s, o);
    if ((threadIdx.x & 31) == 0) red[threadIdx.x >> 5] = s;
    __syncthreads();
    if (threadIdx.x < 8) {
        s = red[threadIdx.x];
        for (int o = 4; o; o >>= 1) s += __shfl_down_sync(0xffu, s, o);
        if (threadIdx.x == 0) g_gpart[id*GSPLIT + q] = s;   // raw sum
    }
}

// ---------------- prepass 2: fold weights + dynamic conv ----------------
#define WEP 65   // smem pitch (bank-conflict-free column reads)

__global__ void __launch_bounds__(256) k_prep(
    const float* __restrict__ lp1w, const float* __restrict__ lp1b,
    const float* __restrict__ rp1w, const float* __restrict__ rp1b,
    const float* __restrict__ nlw,  const float* __restrict__ nlb,
    const float* __restrict__ nrw,  const float* __restrict__ nrb,
    const float* __restrict__ lp2w, const float* __restrict__ lp2b,
    const float* __restrict__ rp2w, const float* __restrict__ rp2b,
    const float* __restrict__ beta, const float* __restrict__ gamma,
    const float* __restrict__ lf1w, const float* __restrict__ lf1b,
    const float* __restrict__ lf2w, const float* __restrict__ lf2b,
    const float* __restrict__ lW,   const float* __restrict__ lbias,
    const float* __restrict__ rf1w, const float* __restrict__ rf1b,
    const float* __restrict__ rf2w, const float* __restrict__ rf2b,
    const float* __restrict__ rW,   const float* __restrict__ rbias)
{
    __shared__ float sWe[CC*WEP];    // Weff, pitch 65
    __shared__ float sPs[CC*CC];     // p2w staged
    __shared__ float sA1[3];
    __shared__ float sAtt[3];

    const int tid  = threadIdx.x;
    const int lane = tid & 31;
    const int wid  = tid >> 5;
    const int bid  = blockIdx.x;

    // ======== blocks 8,9: LN fold ========
    if (bid >= 8) {
        int side = bid - 8;
        const float* pw = side ? rp1w : lp1w;
        const float* pb = side ? rp1b : lp1b;
        const float* nw = side ? nrw  : nlw;
        const float* nb = side ? nrb  : nlb;

        for (int idx = tid; idx < CC*CC; idx += 256) {
            int c = idx >> 6, o = idx & 63;
            g_WT1[side*CC*CC + idx] = pw[o*CC + c] * nw[c];
        }
        for (int j = 0; j < 8; j++) {
            int o = wid * 8 + j;
            float wv0 = pw[o*CC + lane], wv1 = pw[o*CC + lane + 32];
            float rs = wv0*nw[lane] + wv1*nw[lane + 32];
            float bb = wv0*nb[lane] + wv1*nb[lane + 32];
            for (int off = 16; off; off >>= 1) {
                rs += __shfl_down_sync(0xffffffffu, rs, off);
                bb += __shfl_down_sync(0xffffffffu, bb, off);
            }
            if (lane == 0) {
                g_rs1[side*CC + o] = rs;
                g_b1 [side*CC + o] = bb + pb[o];
            }
        }
        return;
    }

    // ======== blocks 0..7: per-(side,b) dynamic-conv folding ========
    const int sb   = bid;
    const int side = sb >> 2, b = sb & 3;
    const float* f1w  = side ? rf1w  : lf1w;
    const float* f1b  = side ? rf1b  : lf1b;
    const float* f2w  = side ? rf2w  : lf2w;
    const float* f2b  = side ? rf2b  : lf2b;
    const float* Wk   = side ? rW    : lW;
    const float* bias = side ? rbias : lbias;
    const float* bg   = side ? gamma : beta;
    const float* p2w  = side ? lp2w  : rp2w;   // out_l path consumes V_r (rp2)!
    const float* p2b  = side ? lp2b  : rp2b;

    if (wid < 3) {
        int base4 = (side*BB*CC + b*CC) * GSPLIT;
        int i0 = base4 + lane*GSPLIT, i1 = base4 + (lane+32)*GSPLIT;
        float g0 = (g_gpart[i0]+g_gpart[i0+1]+g_gpart[i0+2]+g_gpart[i0+3]) * (1.f/HW);
        float g1 = (g_gpart[i1]+g_gpart[i1+1]+g_gpart[i1+2]+g_gpart[i1+3]) * (1.f/HW);
        float s = f1w[wid*CC + lane]*g0 + f1w[wid*CC + lane + 32]*g1;
        for (int off = 16; off; off >>= 1) s += __shfl_down_sync(0xffffffffu, s, off);
        if (lane == 0) sA1[wid] = fmaxf(s + f1b[wid], 0.f);
    }
    for (int idx = tid; idx < CC*CC; idx += 256) sPs[idx] = p2w[idx];
    __syncthreads();

    if (tid == 0) {
        float a2[3];
        #pragma unroll
        for (int k = 0; k < 3; k++) {
            float s = f2b[k];
            #pragma unroll
            for (int j = 0; j < 3; j++) s += f2w[k*3 + j] * sA1[j];
            a2[k] = s;
        }
        float mx = fmaxf(a2[0], fmaxf(a2[1], a2[2]));
        float e0 = expf(a2[0]-mx), e1 = expf(a2[1]-mx), e2 = expf(a2[2]-mx);
        float inv = 1.f / (e0 + e1 + e2);
        sAtt[0] = e0*inv; sAtt[1] = e1*inv; sAtt[2] = e2*inv;
    }
    __syncthreads();

    const float at0 = sAtt[0], at1 = sAtt[1], at2 = sAtt[2];

    for (int idx = tid; idx < CC*CC; idx += 256) {
        int o = idx >> 6, i = idx & 63;
        float w = (at0*Wk[idx] + at1*Wk[CC*CC + idx] + at2*Wk[2*CC*CC + idx]) * bg[i];
        sWe[o*WEP + i] = w;
    }
    __syncthreads();

    // MT[c][o] = sum_i We[o][i] * p2w[i][c]
    {
        int o  = tid & 63;
        int c0 = (tid >> 6) << 4;
        float4 acc0 = {0,0,0,0}, acc1 = {0,0,0,0}, acc2 = {0,0,0,0}, acc3 = {0,0,0,0};
        #pragma unroll 8
        for (int i = 0; i < CC; i++) {
            float w = sWe[o*WEP + i];
            const float4* pr = reinterpret_cast<const float4*>(sPs + i*CC + c0);
            float4 p0 = pr[0], p1 = pr[1], p2 = pr[2], p3 = pr[3];
            acc0.x += w*p0.x; acc0.y += w*p0.y; acc0.z += w*p0.z; acc0.w += w*p0.w;
            acc1.x += w*p1.x; acc1.y += w*p1.y; acc1.z += w*p1.z; acc1.w += w*p1.w;
            acc2.x += w*p2.x; acc2.y += w*p2.y; acc2.z += w*p2.z; acc2.w += w*p2.w;
            acc3.x += w*p3.x; acc3.y += w*p3.y; acc3.z += w*p3.z; acc3.w += w*p3.w;
        }
        float accs[16] = {acc0.x,acc0.y,acc0.z,acc0.w, acc1.x,acc1.y,acc1.z,acc1.w,
                          acc2.x,acc2.y,acc2.z,acc2.w, acc3.x,acc3.y,acc3.z,acc3.w};
        float* dst = g_MT + sb*CC*CC;
        #pragma unroll
        for (int j = 0; j < 16; j++) dst[(c0 + j)*CC + o] = accs[j];
    }

    if (tid < CC) {
        int o = tid;
        float s = at0*bias[o] + at1*bias[CC + o] + at2*bias[2*CC + o];
        #pragma unroll 8
        for (int i = 0; i < CC; i++) s += sWe[o*WEP + i] * p2b[i];
        g_cvec[sb*CC + o] = s;
    }
}

// ---------------- prepass 3: G matrix + correction vectors/scalars ----------------
__global__ void __launch_bounds__(256) k_prep2() {
    __shared__ float sWl[CC*WEP];
    __shared__ float sWr[CC*WEP];
    const int tid = threadIdx.x, bid = blockIdx.x;
    for (int idx = tid; idx < CC*CC; idx += 256) {
        int c = idx >> 6, o = idx & 63;
        sWl[c*WEP + o] = g_WT1[idx];
        sWr[c*WEP + o] = g_WT1[CC*CC + idx];
    }
    __syncthreads();

    if (bid < 4) {
        int c   = tid & 63;
        int cp0 = bid*16 + (tid >> 6)*4;
        float a0=0,a1=0,a2=0,a3=0;
        #pragma unroll 8
        for (int o = 0; o < CC; o++) {
            float wl = sWl[c*WEP + o];
            a0 += wl * sWr[(cp0+0)*WEP + o];
            a1 += wl * sWr[(cp0+1)*WEP + o];
            a2 += wl * sWr[(cp0+2)*WEP + o];
            a3 += wl * sWr[(cp0+3)*WEP + o];
        }
        g_G[(cp0+0)*CC + c] = a0;
        g_G[(cp0+1)*CC + c] = a1;
        g_G[(cp0+2)*CC + c] = a2;
        g_G[(cp0+3)*CC + c] = a3;
    } else {
        __shared__ float sr[4*CC];   // rsl, rsr, b1l, b1r
        if (tid < 64) {
            sr[tid]       = g_rs1[tid];
            sr[64 + tid]  = g_rs1[CC + tid];
            sr[128 + tid] = g_b1[tid];
            sr[192 + tid] = g_b1[CC + tid];
        }
        __syncthreads();
        if (tid < 64) {
            int c = tid;
            float vA=0,vB=0,vC=0,vD=0;
            #pragma unroll 8
            for (int o = 0; o < CC; o++) {
                float wl = sWl[c*WEP + o], wr = sWr[c*WEP + o];
                vA += wl * sr[64 + o];    // W1l^T rs_r
                vB += wl * sr[192 + o];   // W1l^T b1_r
                vC += wr * sr[o];         // W1r^T rs_l
                vD += wr * sr[128 + o];   // W1r^T b1_l
            }
            g_vec[c] = vA; g_vec[64+c] = vB; g_vec[128+c] = vC; g_vec[192+c] = vD;
        }
        int wid = tid >> 5, lane = tid & 31;
        if (wid < 4) {
            const float *x1, *x2;
            if      (wid == 0) { x1 = sr;       x2 = sr + 64;  }  // srr
            else if (wid == 1) { x1 = sr;       x2 = sr + 192; }  // srb
            else if (wid == 2) { x1 = sr + 128; x2 = sr + 64;  }  // sbr
            else               { x1 = sr + 128; x2 = sr + 192; }  // sbb
            float s = x1[lane]*x2[lane] + x1[lane+32]*x2[lane+32];
            for (int off = 16; off; off >>= 1) s += __shfl_down_sync(0xffffffffu, s, off);
            if (lane == 0) g_scal[wid] = s;
        }
    }
}

// ---------------- fused main kernel ----------------
// GEMM micro-kernel: 160 threads as 8(oq) x 20(wq); each thread computes an
// 8(o) x 4(w) tile. Per c-iter: 2 LDG.128 (weights, warp-broadcast) +
// 1 LDS.128 (x) + 32 FFMA  ->  1.5 B/FMA.
__device__ __forceinline__ void gemm_tile8(
    const float* __restrict__ WTm, const float* __restrict__ xs,
    float* __restrict__ os, int t)     // t in 0..159
{
    int oq = t / 20, wq = t - 20*oq;
    int o0 = oq << 3, w0 = wq << 2;
    float4 a0 = {0,0,0,0}, a1 = {0,0,0,0}, a2 = {0,0,0,0}, a3 = {0,0,0,0};
    float4 a4 = {0,0,0,0}, a5 = {0,0,0,0}, a6 = {0,0,0,0}, a7 = {0,0,0,0};

    #pragma unroll 4
    for (int c = 0; c < CC; c++) {
        const float* wp = WTm + (c << 6) + o0;
        float4 wv0 = *reinterpret_cast<const float4*>(wp);
        float4 wv1 = *reinterpret_cast<const float4*>(wp + 4);
        float4 xv  = *reinterpret_cast<const float4*>(xs + c*PIT + w0);
        a0.x += wv0.x*xv.x; a0.y += wv0.x*xv.y; a0.z += wv0.x*xv.z; a0.w += wv0.x*xv.w;
        a1.x += wv0.y*xv.x; a1.y += wv0.y*xv.y; a1.z += wv0.y*xv.z; a1.w += wv0.y*xv.w;
        a2.x += wv0.z*xv.x; a2.y += wv0.z*xv.y; a2.z += wv0.z*xv.z; a2.w += wv0.z*xv.w;
        a3.x += wv0.w*xv.x; a3.y += wv0.w*xv.y; a3.z += wv0.w*xv.z; a3.w += wv0.w*xv.w;
        a4.x += wv1.x*xv.x; a4.y += wv1.x*xv.y; a4.z += wv1.x*xv.z; a4.w += wv1.x*xv.w;
        a5.x += wv1.y*xv.x; a5.y += wv1.y*xv.y; a5.z += wv1.y*xv.z; a5.w += wv1.y*xv.w;
        a6.x += wv1.z*xv.x; a6.y += wv1.z*xv.y; a6.z += wv1.z*xv.z; a6.w += wv1.z*xv.w;
        a7.x += wv1.w*xv.x; a7.y += wv1.w*xv.y; a7.z += wv1.w*xv.z; a7.w += wv1.w*xv.w;
    }
    *reinterpret_cast<float4*>(os + (o0+0)*PIT + w0) = a0;
    *reinterpret_cast<float4*>(os + (o0+1)*PIT + w0) = a1;
    *reinterpret_cast<float4*>(os + (o0+2)*PIT + w0) = a2;
    *reinterpret_cast<float4*>(os + (o0+3)*PIT + w0) = a3;
    *reinterpret_cast<float4*>(os + (o0+4)*PIT + w0) = a4;
    *reinterpret_cast<float4*>(os + (o0+5)*PIT + w0) = a5;
    *reinterpret_cast<float4*>(os + (o0+6)*PIT + w0) = a6;
    *reinterpret_cast<float4*>(os + (o0+7)*PIT + w0) = a7;
}

__global__ void __launch_bounds__(NTHR, 2) k_main(
    const float* __restrict__ xl_g, const float* __restrict__ xr_g,
    float* __restrict__ out)
{
    extern __shared__ float sm[];
    float* xls  = sm;
    float* xrs  = sm + 1*CC*PIT;
    float* qa   = sm + 2*CC*PIT;   // Z then Pr
    float* qb   = sm + 3*CC*PIT;   // Pl
    float* muls = sm + 4*CC*PIT;
    float* invl = muls + WT;
    float* murs = invl + WT;
    float* invr = murs + WT;
    float* Ssm  = invr + WT;       // 800
    float* Ar   = Ssm  + NSUB*100; // 800
    float* Al   = Ar   + NSUB*100; // 800
    float* svec = Al   + NSUB*100; // 256 (vA,vB,vC,vD)
    float* sdA  = svec + 4*CC;     // 80
    float* sdB  = sdA + WT;
    float* sdC  = sdB + WT;
    float* sdD  = sdC + WT;

    int gid = blockIdx.x;
    int g   = gid & 3;
    int h   = (gid >> 2) % HH;
    int b   = gid / (4*HH);
    int tid = threadIdx.x;
    size_t base = (size_t)b * (CC*HW) + (size_t)h * WW + (size_t)g * WT;

    // stage 1: load tiles (float4) + correction vectors
    if (tid < 4*CC) svec[tid] = g_vec[tid];
    for (int idx = tid; idx < CC*WT/4; idx += NTHR) {
        int c = idx / 20, w4 = idx - c*20;
        size_t go = base + (size_t)c*HW + w4*4;
        float4 vl = *reinterpret_cast<const float4*>(xl_g + go);
        float4 vr = *reinterpret_cast<const float4*>(xr_g + go);
        *reinterpret_cast<float4*>(xls + c*PIT + w4*4) = vl;
        *reinterpret_cast<float4*>(xrs + c*PIT + w4*4) = vr;
    }
    __syncthreads();

    // stage 2+3 overlapped:
    //   warps 0-4 (tid<160)  : Z = G @ xr   (8o x 4w tiles)
    //   warps 5-9 (tid>=160) : per-column LN stats + correction dots
    if (tid < 160) {
        gemm_tile8(g_G, xrs, qa, tid);    // Z[c][v]
    } else {
        int idx2 = tid - 160;
        int side = idx2 / WT, w = idx2 - side*WT;
        const float* xs = side ? xrs : xls;
        const float* v0 = svec + side*128;
        float s = 0.f, s2 = 0.f, a0 = 0.f, a1 = 0.f;
        #pragma unroll
        for (int c = 0; c < CC; c++) {
            float v = xs[c*PIT + w];
            s += v; s2 += v*v;
            a0 += v0[c]      * v;
            a1 += v0[64 + c] * v;
        }
        float mu  = s * (1.f/CC);
        float var = s2 * (1.f/CC) - mu*mu;
        float ivv = rsqrtf(var + EPSV);
        if (side) { murs[w] = mu; invr[w] = ivv; sdC[w] = a0; sdD[w] = a1; }
        else      { muls[w] = mu; invl[w] = ivv; sdA[w] = a0; sdB[w] = a1; }
    }
    __syncthreads();

    // stage 4: attention scores via S0 = xl^T Z + rank-1 LN corrections
    if (tid < 200) {
        int n = tid / 25, r = tid - 25*n;
        int u0 = (r/5)*2, v0 = (r%5)*2;
        const float* A_ = xls + n*10;
        const float* B_ = qa  + n*10;
        float a00=0, a01=0, a10=0, a11=0;
        #pragma unroll 8
        for (int c = 0; c < CC; c++) {
            float l0 = A_[c*PIT + u0], l1 = A_[c*PIT + u0 + 1];
            float r0 = B_[c*PIT + v0], r1 = B_[c*PIT + v0 + 1];
            a00 += l0*r0; a01 += l0*r1; a10 += l1*r0; a11 += l1*r1;
        }
        int wu = n*10 + u0, wv = n*10 + v0;
        float il0 = invl[wu],   il1 = invl[wu+1];
        float ml0 = il0*muls[wu], ml1 = il1*muls[wu+1];
        float dA0 = sdA[wu], dA1 = sdA[wu+1];
        float dB0 = sdB[wu], dB1 = sdB[wu+1];
        float ir0 = invr[wv],   ir1 = invr[wv+1];
        float mr0 = ir0*murs[wv], mr1 = ir1*murs[wv+1];
        float dC0 = sdC[wv], dC1 = sdC[wv+1];
        float dD0 = sdD[wv], dD1 = sdD[wv+1];
        float srr = g_scal[0], srb = g_scal[1], sbr = g_scal[2], sbb = g_scal[3];
        const float sc = 0.125f;          // C^-0.5

        float* Sp = Ssm + n*100;
        Sp[ u0   *10 + v0    ] = sc * (il0*ir0*a00 + il0*dB0 - il0*mr0*dA0
                                       + ir0*dD0 - ir0*ml0*dC0
                                       + ml0*mr0*srr - ml0*srb - mr0*sbr + sbb);
        Sp[ u0   *10 + v0 + 1] = sc * (il0*ir1*a01 + il0*dB0 - il0*mr1*dA0
                                       + ir1*dD1 - ir1*ml0*dC1
                                       + ml0*mr1*srr - ml0*srb - mr1*sbr + sbb);
        Sp[(u0+1)*10 + v0    ] = sc * (il1*ir0*a10 + il1*dB1 - il1*mr0*dA1
                                       + ir0*dD0 - ir0*ml1*dC0
                                       + ml1*mr0*srr - ml1*srb - mr0*sbr + sbb);
        Sp[(u0+1)*10 + v0 + 1] = sc * (il1*ir1*a11 + il1*dB1 - il1*mr1*dA1
                                       + ir1*dD1 - ir1*ml1*dC1
                                       + ml1*mr1*srr - ml1*srb - mr1*sbr + sbb);
    }
    __syncthreads();

    // stage 5: dual softmax (rows -> Ar, cols -> Al)
    if (tid < 80) {
        int n = tid / 10, u = tid - 10*n;
        const float* Sp = Ssm + n*100 + u*10;
        float m = Sp[0];
        #pragma unroll
        for (int v = 1; v < 10; v++) m = fmaxf(m, Sp[v]);
        float e[10], s = 0.f;
        #pragma unroll
        for (int v = 0; v < 10; v++) { e[v] = __expf(Sp[v]-m); s += e[v]; }
        float inv = 1.f/s;
        float* dst = Ar + n*100 + u*10;
        #pragma unroll
        for (int v = 0; v < 10; v++) dst[v] = e[v]*inv;
    } else if (tid < 160) {
        int t = tid - 80;
        int n = t / 10, v = t - 10*n;
        const float* Sp = Ssm + n*100 + v;
        float m = Sp[0];
        #pragma unroll
        for (int u = 1; u < 10; u++) m = fmaxf(m, Sp[u*10]);
        float e[10], s = 0.f;
        #pragma unroll
        for (int u = 0; u < 10; u++) { e[u] = __expf(Sp[u*10]-m); s += e[u]; }
        float inv = 1.f/s;
        float* dst = Al + n*100 + v;
        #pragma unroll
        for (int u = 0; u < 10; u++) dst[u*10] = e[u]*inv;
    }
    __syncthreads();

    // stage 6: P projections, two GEMMs concurrently
    //   warps 0-4: Pr = MT_l @ xr -> qa ; warps 5-9: Pl = MT_r @ xl -> qb
    if (tid < 160) gemm_tile8(g_MT + (0*BB + b)*CC*CC, xrs, qa, tid);
    else           gemm_tile8(g_MT + (1*BB + b)*CC*CC, xls, qb, tid - 160);
    __syncthreads();

    // stage 7: aggregate + residual, in place into xls/xrs (256 threads, 4o x 5w)
    if (tid < 256) {
        int oq = tid >> 4, wq = tid & 15;
        int o0 = oq << 2, w0 = wq * 5;
        int n  = w0 / 10;
        int ub = w0 - n*10;                  // 0 or 5
        const float* Arn = Ar + n*100;
        const float* Aln = Al + n*100;
        #pragma unroll
        for (int i = 0; i < 4; i++) {
            int o = o0 + i;
            float cl = g_cvec[b*CC + o];
            float cr = g_cvec[(BB + b)*CC + o];
            float pr[10], pl[10];
            #pragma unroll
            for (int v = 0; v < 10; v++) {
                pr[v] = qa[o*PIT + n*10 + v];
                pl[v] = qb[o*PIT + n*10 + v];
            }
            #pragma unroll
            for (int j = 0; j < 5; j++) {
                int u = ub + j;
                float sl = cl, sr = cr;
                #pragma unroll
                for (int v = 0; v < 10; v++) {
                    sl += Arn[u*10 + v] * pr[v];   // out_l[o,u] = sum_v A_r2l[u,v] Pr[o,v]
                    sr += Aln[v*10 + u] * pl[v];   // out_r[o,u] = sum_uu A_l2r[uu,u] Pl[o,uu]
                }
                xls[o*PIT + w0 + j] += sl;
                xrs[o*PIT + w0 + j] += sr;
            }
        }
    }
    __syncthreads();

    // stage 8: coalesced float4 writeback
    const size_t OUTOFF = (size_t)BB*CC*HW;
    for (int idx = tid; idx < CC*WT/4; idx += NTHR) {
        int c = idx / 20, w4 = idx - c*20;
        size_t go = base + (size_t)c*HW + w4*4;
        *reinterpret_cast<float4*>(out + go) =
            *reinterpret_cast<const float4*>(xls + c*PIT + w4*4);
        *reinterpret_cast<float4*>(out + OUTOFF + go) =
            *reinterpret_cast<const float4*>(xrs + c*PIT + w4*4);
    }
}

// ---------------- launch ----------------
extern "C" void kernel_launch(void* const* d_in, const int* in_sizes, int n_in,
                              void* d_out, int out_size) {
    const float* xl    = (const float*)d_in[0];
    const float* xr    = (const float*)d_in[1];
    const float* nlw   = (const float*)d_in[2];
    const float* nlb   = (const float*)d_in[3];
    const float* nrw   = (const float*)d_in[4];
    const float* nrb   = (const float*)d_in[5];
    const float* lp1w  = (const float*)d_in[6];
    const float* lp1b  = (const float*)d_in[7];
    const float* rp1w  = (const float*)d_in[8];
    const float* rp1b  = (const float*)d_in[9];
    const float* lp2w  = (const float*)d_in[10];
    const float* lp2b  = (const float*)d_in[11];
    const float* rp2w  = (const float*)d_in[12];
    const float* rp2b  = (const float*)d_in[13];
    const float* beta  = (const float*)d_in[14];
    const float* gamma = (const float*)d_in[15];
    const float* lf1w  = (const float*)d_in[16];
    const float* lf1b  = (const float*)d_in[17];
    const float* lf2w  = (const float*)d_in[18];
    const float* lf2b  = (const float*)d_in[19];
    const float* lW    = (const float*)d_in[20];
    const float* lbias = (const float*)d_in[21];
    const float* rf1w  = (const float*)d_in[22];
    const float* rf1b  = (const float*)d_in[23];
    const float* rf2w  = (const float*)d_in[24];
    const float* rf2b  = (const float*)d_in[25];
    const float* rW    = (const float*)d_in[26];
    const float* rbias = (const float*)d_in[27];
    float* out = (float*)d_out;

    const int SMEM_BYTES = (4*CC*PIT + 4*WT + 3*NSUB*100 + 4*CC + 4*WT) * sizeof(float); // 99,200

    cudaFuncSetAttribute(k_main, cudaFuncAttributeMaxDynamicSharedMemorySize, SMEM_BYTES);

    k_gap <<<2*BB*CC*GSPLIT, 256>>>(xl, xr);
    k_prep<<<10, 256>>>(lp1w, lp1b, rp1w, rp1b, nlw, nlb, nrw, nrb,
                        lp2w, lp2b, rp2w, rp2b, beta, gamma,
                        lf1w, lf1b, lf2w, lf2b, lW, lbias,
                        rf1w, rf1b, rf2w, rf2b, rW, rbias);
    k_prep2<<<5, 256>>>();
    k_main<<<BB*HH*(WW/WT), NTHR, SMEM_BYTES>>>(xl, xr, out);
}

// round 17
// speedup vs baseline: 2.9649x; 1.0346x over previous
#include <cuda_runtime.h>

// ---------------- problem constants ----------------
#define BB   4
#define CC   64
#define HH   180
#define WW   320
#define HW   57600          // H*W
#define WT   80             // width tile per CTA (8 sub-chunks of 10)
#define PIT  84             // smem pitch (multiple of 4 for float4 LDS)
#define NSUB 8
#define EPSV 1e-6f
#define GSPLIT 4
#define NTHR 320

// ---------------- device scratch (no allocations allowed) ----------------
__device__ float g_gpart[2*BB*CC*GSPLIT];  // partial sums for gap
__device__ float g_MT  [2*BB*CC*CC];     // [side*4+b][c][o]  (Weff @ p2_w)^T
__device__ float g_cvec[2*BB*CC];        // Weff@p2_b + bagg
__device__ float g_G   [CC*CC];          // [c'][c] : G[c][c'] = sum_o W1l[o,c] W1r[o,c']
__device__ float g_vec [4*CC];           // vA, vB, vC, vD
__device__ float g_scal[4];              // srr, srb, sbr, sbb

// ---------------- prepass 1: global average pool (partials) ----------------
__global__ void k_gap(const float* __restrict__ xl, const float* __restrict__ xr) {
    int blk = blockIdx.x;                        // 0..2047
    int id = blk >> 2, q = blk & 3;
    const float* x = (id < BB*CC) ? xl : xr;
    int rem = id & (BB*CC - 1);
    const float4* p = reinterpret_cast<const float4*>(
        x + (size_t)rem * HW + (size_t)q * (HW/GSPLIT));
    float s = 0.f;
    for (int i = threadIdx.x; i < HW/(4*GSPLIT); i += blockDim.x) {
        float4 v = p[i];
        s += (v.x + v.y) + (v.z + v.w);
    }
    __shared__ float red[8];
    for (int o = 16; o; o >>= 1) s += __shfl_down_sync(0xffffffffu, s, o);
    if ((threadIdx.x & 31) == 0) red[threadIdx.x >> 5] = s;
    __syncthreads();
    if (threadIdx.x < 8) {
        s = red[threadIdx.x];
        for (int o = 4; o; o >>= 1) s += __shfl_down_sync(0xffu, s, o);
        if (threadIdx.x == 0) g_gpart[id*GSPLIT + q] = s;   // raw sum
    }
}

// ---------------- prepass 2 (merged): dyn-conv fold + G + vectors ----------------
// grid = 13 blocks x 256 threads.
//   blocks 0..7  : sb = side*4+b -> att mixture, Weff (smem), MT = Weff@p2w, cvec
//   blocks 8..11 : G = W1l^T W1r rows (local LN fold, no cross-block dependency)
//   block  12    : correction vectors + scalars (local LN fold + rs/b1)
#define WEP 65   // smem pitch (bank-conflict-free column reads)

__global__ void __launch_bounds__(256) k_prepall(
    const float* __restrict__ lp1w, const float* __restrict__ lp1b,
    const float* __restrict__ rp1w, const float* __restrict__ rp1b,
    const float* __restrict__ nlw,  const float* __restrict__ nlb,
    const float* __restrict__ nrw,  const float* __restrict__ nrb,
    const float* __restrict__ lp2w, const float* __restrict__ lp2b,
    const float* __restrict__ rp2w, const float* __restrict__ rp2b,
    const float* __restrict__ beta, const float* __restrict__ gamma,
    const float* __restrict__ lf1w, const float* __restrict__ lf1b,
    const float* __restrict__ lf2w, const float* __restrict__ lf2b,
    const float* __restrict__ lW,   const float* __restrict__ lbias,
    const float* __restrict__ rf1w, const float* __restrict__ rf1b,
    const float* __restrict__ rf2w, const float* __restrict__ rf2b,
    const float* __restrict__ rW,   const float* __restrict__ rbias)
{
    __shared__ float sWe[CC*WEP];    // Weff  (blocks 0-7) | W1l fold (blocks 8-12)
    __shared__ float sPs[CC*WEP];    // p2w   (blocks 0-7) | W1r fold (blocks 8-12)
    __shared__ float sA1[3];
    __shared__ float sAtt[3];
    __shared__ float sr[4*CC];       // rsl, rsr, b1l, b1r (block 12)

    const int tid  = threadIdx.x;
    const int lane = tid & 31;
    const int wid  = tid >> 5;
    const int bid  = blockIdx.x;

    // ======== blocks 8..12: G matrix / vectors, with local LN fold ========
    if (bid >= 8) {
        for (int idx = tid; idx < CC*CC; idx += 256) {
            int c = idx >> 6, o = idx & 63;
            sWe[c*WEP + o] = lp1w[o*CC + c] * nlw[c];   // W1l[o][c]
            sPs[c*WEP + o] = rp1w[o*CC + c] * nrw[c];   // W1r[o][c]
        }
        __syncthreads();

        if (bid < 12) {
            // g_G[c'][c] = sum_o W1l[o][c] * W1r[o][c']
            int gb  = bid - 8;
            int c   = tid & 63;
            int cp0 = gb*16 + (tid >> 6)*4;
            float a0=0,a1=0,a2=0,a3=0;
            #pragma unroll 8
            for (int o = 0; o < CC; o++) {
                float wl = sWe[c*WEP + o];
                a0 += wl * sPs[(cp0+0)*WEP + o];
                a1 += wl * sPs[(cp0+1)*WEP + o];
                a2 += wl * sPs[(cp0+2)*WEP + o];
                a3 += wl * sPs[(cp0+3)*WEP + o];
            }
            g_G[(cp0+0)*CC + c] = a0;
            g_G[(cp0+1)*CC + c] = a1;
            g_G[(cp0+2)*CC + c] = a2;
            g_G[(cp0+3)*CC + c] = a3;
        } else {
            // rs/b1 locally: rs[o] = sum_c W1[o][c]; b1[o] = pb[o] + sum_c pw[o][c]*nb[c]
            if (tid < 128) {
                int side = tid >> 6, o = tid & 63;
                const float* pw = side ? rp1w : lp1w;
                const float* pb = side ? rp1b : lp1b;
                const float* nb = side ? nrb  : nlb;
                const float* sW = side ? sPs  : sWe;
                float rs = 0.f, bb = pb[o];
                #pragma unroll 8
                for (int c = 0; c < CC; c++) {
                    rs += sW[c*WEP + o];
                    bb += pw[o*CC + c] * nb[c];
                }
                sr[side*64 + o]       = rs;
                sr[128 + side*64 + o] = bb;
            }
            __syncthreads();
            if (tid < 64) {
                int c = tid;
                float vA=0,vB=0,vC=0,vD=0;
                #pragma unroll 8
                for (int o = 0; o < CC; o++) {
                    float wl = sWe[c*WEP + o], wr = sPs[c*WEP + o];
                    vA += wl * sr[64 + o];    // W1l^T rs_r
                    vB += wl * sr[192 + o];   // W1l^T b1_r
                    vC += wr * sr[o];         // W1r^T rs_l
                    vD += wr * sr[128 + o];   // W1r^T b1_l
                }
                g_vec[c] = vA; g_vec[64+c] = vB; g_vec[128+c] = vC; g_vec[192+c] = vD;
            }
            if (wid < 4) {
                const float *x1, *x2;
                if      (wid == 0) { x1 = sr;       x2 = sr + 64;  }  // srr
                else if (wid == 1) { x1 = sr;       x2 = sr + 192; }  // srb
                else if (wid == 2) { x1 = sr + 128; x2 = sr + 64;  }  // sbr
                else               { x1 = sr + 128; x2 = sr + 192; }  // sbb
                float s = x1[lane]*x2[lane] + x1[lane+32]*x2[lane+32];
                for (int off = 16; off; off >>= 1) s += __shfl_down_sync(0xffffffffu, s, off);
                if (lane == 0) g_scal[wid] = s;
            }
        }
        return;
    }

    // ======== blocks 0..7: per-(side,b) dynamic-conv folding ========
    const int sb   = bid;
    const int side = sb >> 2, b = sb & 3;
    const float* f1w  = side ? rf1w  : lf1w;
    const float* f1b  = side ? rf1b  : lf1b;
    const float* f2w  = side ? rf2w  : lf2w;
    const float* f2b  = side ? rf2b  : lf2b;
    const float* Wk   = side ? rW    : lW;
    const float* bias = side ? rbias : lbias;
    const float* bg   = side ? gamma : beta;
    const float* p2w  = side ? lp2w  : rp2w;   // out_l path consumes V_r (rp2)!
    const float* p2b  = side ? lp2b  : rp2b;

    if (wid < 3) {
        int base4 = (side*BB*CC + b*CC) * GSPLIT;
        int i0 = base4 + lane*GSPLIT, i1 = base4 + (lane+32)*GSPLIT;
        float g0 = (g_gpart[i0]+g_gpart[i0+1]+g_gpart[i0+2]+g_gpart[i0+3]) * (1.f/HW);
        float g1 = (g_gpart[i1]+g_gpart[i1+1]+g_gpart[i1+2]+g_gpart[i1+3]) * (1.f/HW);
        float s = f1w[wid*CC + lane]*g0 + f1w[wid*CC + lane + 32]*g1;
        for (int off = 16; off; off >>= 1) s += __shfl_down_sync(0xffffffffu, s, off);
        if (lane == 0) sA1[wid] = fmaxf(s + f1b[wid], 0.f);
    }
    for (int idx = tid; idx < CC*CC; idx += 256) sPs[idx] = p2w[idx];
    __syncthreads();

    if (tid == 0) {
        float a2[3];
        #pragma unroll
        for (int k = 0; k < 3; k++) {
            float s = f2b[k];
            #pragma unroll
            for (int j = 0; j < 3; j++) s += f2w[k*3 + j] * sA1[j];
            a2[k] = s;
        }
        float mx = fmaxf(a2[0], fmaxf(a2[1], a2[2]));
        float e0 = expf(a2[0]-mx), e1 = expf(a2[1]-mx), e2 = expf(a2[2]-mx);
        float inv = 1.f / (e0 + e1 + e2);
        sAtt[0] = e0*inv; sAtt[1] = e1*inv; sAtt[2] = e2*inv;
    }
    __syncthreads();

    const float at0 = sAtt[0], at1 = sAtt[1], at2 = sAtt[2];

    for (int idx = tid; idx < CC*CC; idx += 256) {
        int o = idx >> 6, i = idx & 63;
        float w = (at0*Wk[idx] + at1*Wk[CC*CC + idx] + at2*Wk[2*CC*CC + idx]) * bg[i];
        sWe[o*WEP + i] = w;
    }
    __syncthreads();

    // MT[c][o] = sum_i We[o][i] * p2w[i][c]
    {
        int o  = tid & 63;
        int c0 = (tid >> 6) << 4;
        float4 acc0 = {0,0,0,0}, acc1 = {0,0,0,0}, acc2 = {0,0,0,0}, acc3 = {0,0,0,0};
        #pragma unroll 8
        for (int i = 0; i < CC; i++) {
            float w = sWe[o*WEP + i];
            const float4* pr = reinterpret_cast<const float4*>(sPs + i*CC + c0);
            float4 p0 = pr[0], p1 = pr[1], p2 = pr[2], p3 = pr[3];
            acc0.x += w*p0.x; acc0.y += w*p0.y; acc0.z += w*p0.z; acc0.w += w*p0.w;
            acc1.x += w*p1.x; acc1.y += w*p1.y; acc1.z += w*p1.z; acc1.w += w*p1.w;
            acc2.x += w*p2.x; acc2.y += w*p2.y; acc2.z += w*p2.z; acc2.w += w*p2.w;
            acc3.x += w*p3.x; acc3.y += w*p3.y; acc3.z += w*p3.z; acc3.w += w*p3.w;
        }
        float accs[16] = {acc0.x,acc0.y,acc0.z,acc0.w, acc1.x,acc1.y,acc1.z,acc1.w,
                          acc2.x,acc2.y,acc2.z,acc2.w, acc3.x,acc3.y,acc3.z,acc3.w};
        float* dst = g_MT + sb*CC*CC;
        #pragma unroll
        for (int j = 0; j < 16; j++) dst[(c0 + j)*CC + o] = accs[j];
    }

    if (tid < CC) {
        int o = tid;
        float s = at0*bias[o] + at1*bias[CC + o] + at2*bias[2*CC + o];
        #pragma unroll 8
        for (int i = 0; i < CC; i++) s += sWe[o*WEP + i] * p2b[i];
        g_cvec[sb*CC + o] = s;
    }
}

// ---------------- fused main kernel ----------------
// GEMM micro-kernel: 160 threads as 8(oq) x 20(wq); each thread computes an
// 8(o) x 4(w) tile. Per c-iter: 2 LDG.128 (weights, warp-broadcast) +
// 1 LDS.128 (x) + 32 FFMA.
__device__ __forceinline__ void gemm_tile8(
    const float* __restrict__ WTm, const float* __restrict__ xs,
    float* __restrict__ os, int t)     // t in 0..159
{
    int oq = t / 20, wq = t - 20*oq;
    int o0 = oq << 3, w0 = wq << 2;
    float4 a0 = {0,0,0,0}, a1 = {0,0,0,0}, a2 = {0,0,0,0}, a3 = {0,0,0,0};
    float4 a4 = {0,0,0,0}, a5 = {0,0,0,0}, a6 = {0,0,0,0}, a7 = {0,0,0,0};

    #pragma unroll 4
    for (int c = 0; c < CC; c++) {
        const float* wp = WTm + (c << 6) + o0;
        float4 wv0 = *reinterpret_cast<const float4*>(wp);
        float4 wv1 = *reinterpret_cast<const float4*>(wp + 4);
        float4 xv  = *reinterpret_cast<const float4*>(xs + c*PIT + w0);
        a0.x += wv0.x*xv.x; a0.y += wv0.x*xv.y; a0.z += wv0.x*xv.z; a0.w += wv0.x*xv.w;
        a1.x += wv0.y*xv.x; a1.y += wv0.y*xv.y; a1.z += wv0.y*xv.z; a1.w += wv0.y*xv.w;
        a2.x += wv0.z*xv.x; a2.y += wv0.z*xv.y; a2.z += wv0.z*xv.z; a2.w += wv0.z*xv.w;
        a3.x += wv0.w*xv.x; a3.y += wv0.w*xv.y; a3.z += wv0.w*xv.z; a3.w += wv0.w*xv.w;
        a4.x += wv1.x*xv.x; a4.y += wv1.x*xv.y; a4.z += wv1.x*xv.z; a4.w += wv1.x*xv.w;
        a5.x += wv1.y*xv.x; a5.y += wv1.y*xv.y; a5.z += wv1.y*xv.z; a5.w += wv1.y*xv.w;
        a6.x += wv1.z*xv.x; a6.y += wv1.z*xv.y; a6.z += wv1.z*xv.z; a6.w += wv1.z*xv.w;
        a7.x += wv1.w*xv.x; a7.y += wv1.w*xv.y; a7.z += wv1.w*xv.z; a7.w += wv1.w*xv.w;
    }
    *reinterpret_cast<float4*>(os + (o0+0)*PIT + w0) = a0;
    *reinterpret_cast<float4*>(os + (o0+1)*PIT + w0) = a1;
    *reinterpret_cast<float4*>(os + (o0+2)*PIT + w0) = a2;
    *reinterpret_cast<float4*>(os + (o0+3)*PIT + w0) = a3;
    *reinterpret_cast<float4*>(os + (o0+4)*PIT + w0) = a4;
    *reinterpret_cast<float4*>(os + (o0+5)*PIT + w0) = a5;
    *reinterpret_cast<float4*>(os + (o0+6)*PIT + w0) = a6;
    *reinterpret_cast<float4*>(os + (o0+7)*PIT + w0) = a7;
}

__global__ void __launch_bounds__(NTHR, 2) k_main(
    const float* __restrict__ xl_g, const float* __restrict__ xr_g,
    float* __restrict__ out)
{
    extern __shared__ float sm[];
    float* xls  = sm;
    float* xrs  = sm + 1*CC*PIT;
    float* qa   = sm + 2*CC*PIT;   // Z then Pr
    float* qb   = sm + 3*CC*PIT;   // Pl
    float* muls = sm + 4*CC*PIT;
    float* invl = muls + WT;
    float* murs = invl + WT;
    float* invr = murs + WT;
    float* Ssm  = invr + WT;       // 800
    float* Ar   = Ssm  + NSUB*100; // 800  A_r2l[n][u][v]
    float* Al   = Ar   + NSUB*100; // 800  A_l2r TRANSPOSED: Al[n][u_out][uu_sum]
    float* svec = Al   + NSUB*100; // 256 (vA,vB,vC,vD)
    float* sdA  = svec + 4*CC;     // 80
    float* sdB  = sdA + WT;
    float* sdC  = sdB + WT;
    float* sdD  = sdC + WT;
    float* scv  = sdD + WT;        // 128 (cvec_l, cvec_r)

    int gid = blockIdx.x;
    int g   = gid & 3;
    int h   = (gid >> 2) % HH;
    int b   = gid / (4*HH);
    int tid = threadIdx.x;
    size_t base = (size_t)b * (CC*HW) + (size_t)h * WW + (size_t)g * WT;

    // stage 1: load tiles (float4) + correction vectors + cvec
    if (tid < 4*CC) svec[tid] = g_vec[tid];
    if (tid >= 192) {                        // threads 192..319 -> 128 slots
        int t2 = tid - 192;                  // 0..127
        int side = t2 >> 6, o = t2 & 63;
        scv[t2] = g_cvec[(side*BB + b)*CC + o];
    }
    for (int idx = tid; idx < CC*WT/4; idx += NTHR) {
        int c = idx / 20, w4 = idx - c*20;
        size_t go = base + (size_t)c*HW + w4*4;
        float4 vl = *reinterpret_cast<const float4*>(xl_g + go);
        float4 vr = *reinterpret_cast<const float4*>(xr_g + go);
        *reinterpret_cast<float4*>(xls + c*PIT + w4*4) = vl;
        *reinterpret_cast<float4*>(xrs + c*PIT + w4*4) = vr;
    }
    __syncthreads();

    // stage 2+3 overlapped:
    //   warps 0-4 (tid<160)  : Z = G @ xr   (8o x 4w tiles)
    //   warps 5-9 (tid>=160) : per-column LN stats + correction dots
    if (tid < 160) {
        gemm_tile8(g_G, xrs, qa, tid);    // Z[c][v]
    } else {
        int idx2 = tid - 160;
        int side = idx2 / WT, w = idx2 - side*WT;
        const float* xs = side ? xrs : xls;
        const float* v0 = svec + side*128;
        float s = 0.f, s2 = 0.f, a0 = 0.f, a1 = 0.f;
        #pragma unroll
        for (int c = 0; c < CC; c++) {
            float v = xs[c*PIT + w];
            s += v; s2 += v*v;
            a0 += v0[c]      * v;
            a1 += v0[64 + c] * v;
        }
        float mu  = s * (1.f/CC);
        float var = s2 * (1.f/CC) - mu*mu;
        float ivv = rsqrtf(var + EPSV);
        if (side) { murs[w] = mu; invr[w] = ivv; sdC[w] = a0; sdD[w] = a1; }
        else      { muls[w] = mu; invl[w] = ivv; sdA[w] = a0; sdB[w] = a1; }
    }
    __syncthreads();

    // stage 4: attention scores via S0 = xl^T Z + rank-1 LN corrections (float2 loads)
    if (tid < 200) {
        int n = tid / 25, r = tid - 25*n;
        int u0 = (r/5)*2, v0 = (r%5)*2;
        float a00=0, a01=0, a10=0, a11=0;
        #pragma unroll 8
        for (int c = 0; c < CC; c++) {
            float2 la = *reinterpret_cast<const float2*>(xls + c*PIT + n*10 + u0);
            float2 rb = *reinterpret_cast<const float2*>(qa  + c*PIT + n*10 + v0);
            a00 += la.x*rb.x; a01 += la.x*rb.y; a10 += la.y*rb.x; a11 += la.y*rb.y;
        }
        int wu = n*10 + u0, wv = n*10 + v0;
        float il0 = invl[wu],   il1 = invl[wu+1];
        float ml0 = il0*muls[wu], ml1 = il1*muls[wu+1];
        float dA0 = sdA[wu], dA1 = sdA[wu+1];
        float dB0 = sdB[wu], dB1 = sdB[wu+1];
        float ir0 = invr[wv],   ir1 = invr[wv+1];
        float mr0 = ir0*murs[wv], mr1 = ir1*murs[wv+1];
        float dC0 = sdC[wv], dC1 = sdC[wv+1];
        float dD0 = sdD[wv], dD1 = sdD[wv+1];
        float srr = g_scal[0], srb = g_scal[1], sbr = g_scal[2], sbb = g_scal[3];
        const float sc = 0.125f;          // C^-0.5

        float* Sp = Ssm + n*100;
        Sp[ u0   *10 + v0    ] = sc * (il0*ir0*a00 + il0*dB0 - il0*mr0*dA0
                                       + ir0*dD0 - ir0*ml0*dC0
                                       + ml0*mr0*srr - ml0*srb - mr0*sbr + sbb);
        Sp[ u0   *10 + v0 + 1] = sc * (il0*ir1*a01 + il0*dB0 - il0*mr1*dA0
                                       + ir1*dD1 - ir1*ml0*dC1
                                       + ml0*mr1*srr - ml0*srb - mr1*sbr + sbb);
        Sp[(u0+1)*10 + v0    ] = sc * (il1*ir0*a10 + il1*dB1 - il1*mr0*dA1
                                       + ir0*dD0 - ir0*ml1*dC0
                                       + ml1*mr0*srr - ml1*srb - mr0*sbr + sbb);
        Sp[(u0+1)*10 + v0 + 1] = sc * (il1*ir1*a11 + il1*dB1 - il1*mr1*dA1
                                       + ir1*dD1 - ir1*ml1*dC1
                                       + ml1*mr1*srr - ml1*srb - mr1*sbr + sbb);
    }
    __syncthreads();

    // stage 5: dual softmax (rows -> Ar ; cols -> Al TRANSPOSED: Al[n][col][row])
    if (tid < 80) {
        int n = tid / 10, u = tid - 10*n;
        const float* Sp = Ssm + n*100 + u*10;
        float m = Sp[0];
        #pragma unroll
        for (int v = 1; v < 10; v++) m = fmaxf(m, Sp[v]);
        float e[10], s = 0.f;
        #pragma unroll
        for (int v = 0; v < 10; v++) { e[v] = __expf(Sp[v]-m); s += e[v]; }
        float inv = 1.f/s;
        float* dst = Ar + n*100 + u*10;
        #pragma unroll
        for (int v = 0; v < 10; v++) dst[v] = e[v]*inv;
    } else if (tid < 160) {
        int t = tid - 80;
        int n = t / 10, v = t - 10*n;
        const float* Sp = Ssm + n*100 + v;
        float m = Sp[0];
        #pragma unroll
        for (int u = 1; u < 10; u++) m = fmaxf(m, Sp[u*10]);
        float e[10], s = 0.f;
        #pragma unroll
        for (int u = 0; u < 10; u++) { e[u] = __expf(Sp[u*10]-m); s += e[u]; }
        float inv = 1.f/s;
        float* dst = Al + n*100 + v*10;     // TRANSPOSED: Al[n][v][u]
        #pragma unroll
        for (int u = 0; u < 10; u++) dst[u] = e[u]*inv;
    }
    __syncthreads();

    // stage 6: P projections, two GEMMs concurrently
    //   warps 0-4: Pr = MT_l @ xr -> qa ; warps 5-9: Pl = MT_r @ xl -> qb
    if (tid < 160) gemm_tile8(g_MT + (0*BB + b)*CC*CC, xrs, qa, tid);
    else           gemm_tile8(g_MT + (1*BB + b)*CC*CC, xls, qb, tid - 160);
    __syncthreads();

    // stage 7: aggregate + residual. Thread <-> (width-column uc, 16-o slab og).
    // A rows loaded once per thread (float2); pr/pl rows float2, warp-broadcast.
    {
        int uc = tid % 80;           // 0..79  (width column)
        int og = tid / 80;           // 0..3   (o slab)
        int n = uc / 10, u = uc - 10*n;
        const float2* ar2 = reinterpret_cast<const float2*>(Ar + n*100 + u*10);
        const float2* al2 = reinterpret_cast<const float2*>(Al + n*100 + u*10);
        float2 ar[5], al[5];
        #pragma unroll
        for (int k = 0; k < 5; k++) { ar[k] = ar2[k]; al[k] = al2[k]; }
        int w = n*10 + u;
        int o0 = og*16;
        #pragma unroll 4
        for (int oi = 0; oi < 16; oi++) {
            int o = o0 + oi;
            const float2* pr2 = reinterpret_cast<const float2*>(qa + o*PIT + n*10);
            const float2* pl2 = reinterpret_cast<const float2*>(qb + o*PIT + n*10);
            float sl = scv[o], srv = scv[64 + o];
            #pragma unroll
            for (int k = 0; k < 5; k++) {
                float2 p = pr2[k];
                sl  += ar[k].x*p.x;  sl  += ar[k].y*p.y;   // out_l[o,u] = sum_v Ar[u,v] Pr[o,v]
                float2 q = pl2[k];
                srv += al[k].x*q.x;  srv += al[k].y*q.y;   // out_r[o,u] = sum_uu AlT[u,uu] Pl[o,uu]
            }
            xls[o*PIT + w] += sl;
            xrs[o*PIT + w] += srv;
        }
    }
    __syncthreads();

    // stage 8: coalesced float4 writeback
    const size_t OUTOFF = (size_t)BB*CC*HW;
    for (int idx = tid; idx < CC*WT/4; idx += NTHR) {
        int c = idx / 20, w4 = idx - c*20;
        size_t go = base + (size_t)c*HW + w4*4;
        *reinterpret_cast<float4*>(out + go) =
            *reinterpret_cast<const float4*>(xls + c*PIT + w4*4);
        *reinterpret_cast<float4*>(out + OUTOFF + go) =
            *reinterpret_cast<const float4*>(xrs + c*PIT + w4*4);
    }
}

// ---------------- launch ----------------
extern "C" void kernel_launch(void* const* d_in, const int* in_sizes, int n_in,
                              void* d_out, int out_size) {
    const float* xl    = (const float*)d_in[0];
    const float* xr    = (const float*)d_in[1];
    const float* nlw   = (const float*)d_in[2];
    const float* nlb   = (const float*)d_in[3];
    const float* nrw   = (const float*)d_in[4];
    const float* nrb   = (const float*)d_in[5];
    const float* lp1w  = (const float*)d_in[6];
    const float* lp1b  = (const float*)d_in[7];
    const float* rp1w  = (const float*)d_in[8];
    const float* rp1b  = (const float*)d_in[9];
    const float* lp2w  = (const float*)d_in[10];
    const float* lp2b  = (const float*)d_in[11];
    const float* rp2w  = (const float*)d_in[12];
    const float* rp2b  = (const float*)d_in[13];
    const float* beta  = (const float*)d_in[14];
    const float* gamma = (const float*)d_in[15];
    const float* lf1w  = (const float*)d_in[16];
    const float* lf1b  = (const float*)d_in[17];
    const float* lf2w  = (const float*)d_in[18];
    const float* lf2b  = (const float*)d_in[19];
    const float* lW    = (const float*)d_in[20];
    const float* lbias = (const float*)d_in[21];
    const float* rf1w  = (const float*)d_in[22];
    const float* rf1b  = (const float*)d_in[23];
    const float* rf2w  = (const float*)d_in[24];
    const float* rf2b  = (const float*)d_in[25];
    const float* rW    = (const float*)d_in[26];
    const float* rbias = (const float*)d_in[27];
    float* out = (float*)d_out;

    const int SMEM_BYTES = (4*CC*PIT + 4*WT + 3*NSUB*100 + 4*CC + 4*WT + 2*CC)
                           * sizeof(float);  // 99,712

    cudaFuncSetAttribute(k_main, cudaFuncAttributeMaxDynamicSharedMemorySize, SMEM_BYTES);

    k_gap    <<<2*BB*CC*GSPLIT, 256>>>(xl, xr);
    k_prepall<<<13, 256>>>(lp1w, lp1b, rp1w, rp1b, nlw, nlb, nrw, nrb,
                           lp2w, lp2b, rp2w, rp2b, beta, gamma,
                           lf1w, lf1b, lf2w, lf2b, lW, lbias,
                           rf1w, rf1b, rf2w, rf2b, rW, rbias);
    k_main<<<BB*HH*(WW/WT), NTHR, SMEM_BYTES>>>(xl, xr, out);
}